// round 7
// baseline (speedup 1.0000x reference)
#include <cuda_runtime.h>
#include <cuda_fp16.h>
#include <cstdint>

#define BB 4
#define SS 2048
#define DD 1024
#define HH 16
#define DKK 64
#define MR (BB*SS)   // 8192

#define MT 128
#define NT 256
#define NCH 32
#define ATILEH 4096          // halves per 128x32 A tile
#define ATILEB 8192
#define BTILEH 8192          // halves per 256x32 B tile
#define BTILEB 16384
#define CHB (2*ATILEB + 2*BTILEB)   // 48KB stage: Ahi|Alo|Bhi|Blo
#define NSTG 3
#define KVP 16               // kv_outer partials

// ---------------- device scratch ----------------
__device__ __half g_wt[4][2][DD*DD];    // weight panels (x32 scaled, split hi/lo), 256-row tiles
__device__ __half g_pan[4][2][MR*DD];   // activation panels (128-row tiles): 0=q 1=k 2=v 3=softmax-out
__device__ float g_qh[MR*DD];
__device__ float g_kh[MR*DD];
__device__ float g_vh[MR*DD];
__device__ float g_Mpart[BB*HH*KVP][DKK*DKK];
__device__ float g_M[BB*HH][DKK*DKK];

// ---------------- helpers ----------------
__device__ __forceinline__ uint32_t smem_u32(const void* p) {
    uint32_t a;
    asm("{ .reg .u64 t; cvta.to.shared.u64 t, %1; cvt.u32.u64 %0, t; }" : "=r"(a) : "l"(p));
    return a;
}
#define MBAR_INIT(a, c) asm volatile("mbarrier.init.shared.b64 [%0], %1;" :: "r"(a), "r"(c) : "memory")
#define MBAR_WAIT(a, ph) do { \
    asm volatile("{\n\t.reg .pred P;\n\tWL%=:\n\t" \
        "mbarrier.try_wait.parity.shared.b64 P, [%0], %1;\n\t" \
        "@!P bra WL%=;\n\t}" :: "r"(a), "r"(ph) : "memory"); } while (0)
#define EXPECT_TX(a, n) asm volatile( \
    "mbarrier.arrive.expect_tx.shared.b64 _, [%0], %1;" :: "r"(a), "r"(n) : "memory")
#define BULK(dst, src, n, bar) asm volatile( \
    "cp.async.bulk.shared::cluster.global.mbarrier::complete_tx::bytes [%0], [%1], %2, [%3];" \
    :: "r"(dst), "l"(src), "r"(n), "r"(bar) : "memory")
#define LDSM4(r, a) asm volatile( \
    "ldmatrix.sync.aligned.m8n8.x4.shared.b16 {%0,%1,%2,%3}, [%4];" \
    : "=r"((r)[0]), "=r"((r)[1]), "=r"((r)[2]), "=r"((r)[3]) : "r"(a))
#define MMAF16(d, a, b0, b1) asm volatile( \
    "mma.sync.aligned.m16n8k16.row.col.f32.f16.f16.f32 " \
    "{%0,%1,%2,%3}, {%4,%5,%6,%7}, {%8,%9}, {%0,%1,%2,%3};" \
    : "+f"((d)[0]), "+f"((d)[1]), "+f"((d)[2]), "+f"((d)[3]) \
    : "r"((a)[0]), "r"((a)[1]), "r"((a)[2]), "r"((a)[3]), "r"(b0), "r"(b1))

// swizzle for 64B rows: XOR 16B-chunk index with row bits [1:2]
__device__ __forceinline__ uint32_t sw64(uint32_t off) {
    return off ^ ((off >> 3) & 0x30);
}

// ---------------------------------------------------------------------------
// weights: scale x32, split+transpose into pre-swizzled fp16 hi/lo 256-row panels
// ---------------------------------------------------------------------------
__global__ void prep_split(const float* __restrict__ wq, const float* __restrict__ wk,
                           const float* __restrict__ wv, const float* __restrict__ wo) {
    int idx = blockIdx.x * blockDim.x + threadIdx.x;   // n*1024 + k
    int n = idx >> 10, k = idx & 1023;
    int h = n >> 6, dk = n & 63;
    int src = h * (DD * DKK) + k * DKK + dk;           // w[h][k][dk]
    uint32_t off = (n & 255) * 64 + (k & 31) * 2;
    size_t d = ((size_t)((n >> 8) * 32 + (k >> 5))) * BTILEH + (sw64(off) >> 1);
    float vals[4] = { wq[src] * 32.0f, wk[src] * 32.0f, wv[src] * 32.0f,
                      wo[n * DD + k] * 32.0f };
    #pragma unroll
    for (int w = 0; w < 4; w++) {
        __half hi = __float2half_rn(vals[w]);
        __half lo = __float2half_rn(vals[w] - __half2float(hi));
        g_wt[w][0][d] = hi;
        g_wt[w][1][d] = lo;
    }
}

// split q,k,v into pre-swizzled fp16 hi/lo 128-row panels; one 16B chunk per thread
__global__ void split3(const float* __restrict__ q, const float* __restrict__ k,
                       const float* __restrict__ v) {
    int idx = blockIdx.x * blockDim.x + threadIdx.x;   // chunk index (8 halves)
    int m = idx >> 7;
    int k0 = (idx & 127) << 3;
    uint32_t off = (m & 127) * 64 + (k0 & 31) * 2;
    size_t d = ((size_t)((m >> 7) * 32 + (k0 >> 5))) * ATILEH + (sw64(off) >> 1);
    size_t s = (size_t)m * DD + k0;
    const float* srcs[3] = { q + s, k + s, v + s };
    #pragma unroll
    for (int w = 0; w < 3; w++) {
        float f[8];
        *(float4*)&f[0] = *(const float4*)(srcs[w]);
        *(float4*)&f[4] = *(const float4*)(srcs[w] + 4);
        __half hi[8], lo[8];
        #pragma unroll
        for (int i = 0; i < 8; i++) {
            hi[i] = __float2half_rn(f[i]);
            lo[i] = __float2half_rn(f[i] - __half2float(hi[i]));
        }
        *(uint4*)&g_pan[w][0][d] = *(uint4*)hi;
        *(uint4*)&g_pan[w][1][d] = *(uint4*)lo;
    }
}

// ---------------------------------------------------------------------------
// 3x-split fp16 mma.sync GEMM, bulk-copy pipeline, CTA 128x256, warp 64x64.
// mode 0: fused QKV (grid.x=12 -> widx = x>>2), mode 1: wo (widx=3).
// ---------------------------------------------------------------------------
__global__ __launch_bounds__(256, 1) void mma_gemm(
        const float* __restrict__ b0p, const float* __restrict__ b1p,
        const float* __restrict__ b2p, const float* __restrict__ bwp,
        float* __restrict__ Oout, int mode) {
    extern __shared__ char smem[];
    int widx, nIdx;
    const float* bias;
    float* C;
    if (mode == 0) {
        widx = blockIdx.x >> 2;
        nIdx = blockIdx.x & 3;
        bias = (widx == 0) ? b0p : (widx == 1) ? b1p : b2p;
        C = (widx == 0) ? g_qh : (widx == 1) ? g_kh : g_vh;
    } else {
        widx = 3;
        nIdx = blockIdx.x;
        bias = bwp;
        C = Oout;
    }
    const __half* Ahi = g_pan[widx][0];
    const __half* Alo = g_pan[widx][1];
    const __half* Bhi = g_wt[widx][0];
    const __half* Blo = g_wt[widx][1];

    const uint32_t s0 = smem_u32(smem);
    const uint32_t mb = s0 + NSTG * CHB;

    const int tid = threadIdx.x;
    const int wid = tid >> 5, lane = tid & 31;
    const int bm = blockIdx.y * MT, bn = nIdx * NT;
    const int m0 = (wid >> 2) * 64;       // 0 or 64
    const int n0 = (wid & 3) * 64;        // 0,64,128,192

    if (tid == 0) { MBAR_INIT(mb, 1); MBAR_INIT(mb + 8, 1); MBAR_INIT(mb + 16, 1); }
    __syncthreads();

    auto issue = [&](int ch, int stg) {
        uint32_t sb = s0 + stg * CHB;
        uint32_t bar = mb + stg * 8;
        EXPECT_TX(bar, (uint32_t)CHB);
        const __half* a0 = Ahi + ((size_t)(blockIdx.y * 32 + ch)) * ATILEH;
        const __half* a1 = Alo + ((size_t)(blockIdx.y * 32 + ch)) * ATILEH;
        const __half* w0 = Bhi + ((size_t)(nIdx * 32 + ch)) * BTILEH;
        const __half* w1 = Blo + ((size_t)(nIdx * 32 + ch)) * BTILEH;
        BULK(sb,                          a0, ATILEB, bar);
        BULK(sb + ATILEB,                 a1, ATILEB, bar);
        BULK(sb + 2 * ATILEB,             w0, BTILEB, bar);
        BULK(sb + 2 * ATILEB + BTILEB,    w1, BTILEB, bar);
    };
    if (tid == 0) { issue(0, 0); issue(1, 1); }

    // ldmatrix lane addressing (64B rows, sw64 swizzle)
    const int rowA = m0 + (lane & 7) + ((lane >> 3) & 1) * 8;
    const uint32_t cA = ((lane >> 4) & 1) * 16;
    const uint32_t xswA = (uint32_t)(rowA & 6) << 3;
    const uint32_t aRow = (uint32_t)rowA * 64;
    const int rowB = n0 + ((lane >> 4) << 3) + (lane & 7);
    const uint32_t cB = ((lane >> 3) & 1) * 16;
    const uint32_t xswB = (uint32_t)(rowB & 6) << 3;
    const uint32_t bRow = (uint32_t)rowB * 64;

    float acc[4][8][4];
    #pragma unroll
    for (int i = 0; i < 4; i++)
        #pragma unroll
        for (int j = 0; j < 8; j++)
            #pragma unroll
            for (int r = 0; r < 4; r++) acc[i][j][r] = 0.0f;

    for (int c = 0; c < NCH; ++c) {
        int stg = c % 3;
        uint32_t sb = s0 + stg * CHB;
        uint32_t sbB = sb + 2 * ATILEB;
        MBAR_WAIT(mb + stg * 8, (c / 3) & 1);

        #pragma unroll
        for (int ks = 0; ks < 2; ks++) {
            const uint32_t aoff = aRow + (((uint32_t)(ks * 32) + cA) ^ xswA);
            const uint32_t boff = bRow + (((uint32_t)(ks * 32) + cB) ^ xswB);
            uint32_t af[4][4], bh[4][4], bl[4][4];
            // A-hi, B-hi
            #pragma unroll
            for (int i = 0; i < 4; i++) LDSM4(af[i], sb + aoff + i * 1024);
            #pragma unroll
            for (int g = 0; g < 4; g++) LDSM4(bh[g], sbB + boff + g * 1024);
            #pragma unroll
            for (int i = 0; i < 4; i++)
                #pragma unroll
                for (int g = 0; g < 4; g++) {
                    MMAF16(acc[i][g * 2 + 0], af[i], bh[g][0], bh[g][1]);
                    MMAF16(acc[i][g * 2 + 1], af[i], bh[g][2], bh[g][3]);
                }
            // A-hi x B-lo
            #pragma unroll
            for (int g = 0; g < 4; g++) LDSM4(bl[g], sbB + BTILEB + boff + g * 1024);
            #pragma unroll
            for (int i = 0; i < 4; i++)
                #pragma unroll
                for (int g = 0; g < 4; g++) {
                    MMAF16(acc[i][g * 2 + 0], af[i], bl[g][0], bl[g][1]);
                    MMAF16(acc[i][g * 2 + 1], af[i], bl[g][2], bl[g][3]);
                }
            // A-lo x B-hi (reuse af regs)
            #pragma unroll
            for (int i = 0; i < 4; i++) LDSM4(af[i], sb + ATILEB + aoff + i * 1024);
            #pragma unroll
            for (int i = 0; i < 4; i++)
                #pragma unroll
                for (int g = 0; g < 4; g++) {
                    MMAF16(acc[i][g * 2 + 0], af[i], bh[g][0], bh[g][1]);
                    MMAF16(acc[i][g * 2 + 1], af[i], bh[g][2], bh[g][3]);
                }
        }
        __syncthreads();
        if (tid == 0 && c + 2 < NCH) issue(c + 2, (c + 2) % 3);
    }

    // ---- epilogue: undo x32 weight scale, add bias ----
    #pragma unroll
    for (int i = 0; i < 4; i++) {
        int row0 = bm + m0 + i * 16 + (lane >> 2);
        #pragma unroll
        for (int jj = 0; jj < 8; jj++) {
            int col = bn + n0 + jj * 8 + (lane & 3) * 2;
            float2 bv = *(const float2*)(bias + col);
            float2 r0, r1;
            r0.x = acc[i][jj][0] * 0.03125f + bv.x;  r0.y = acc[i][jj][1] * 0.03125f + bv.y;
            r1.x = acc[i][jj][2] * 0.03125f + bv.x;  r1.y = acc[i][jj][3] * 0.03125f + bv.y;
            *(float2*)(C + (size_t)row0 * DD + col) = r0;
            *(float2*)(C + (size_t)(row0 + 8) * DD + col) = r1;
        }
    }
}

// ---------------------------------------------------------------------------
// partial Kh^T @ Vh over 128-row s-chunks: grid (64, 16)
// ---------------------------------------------------------------------------
__global__ __launch_bounds__(256) void kv_outer() {
    int bh = blockIdx.x;
    int b = bh >> 4, h = bh & 15;
    int s_base = blockIdx.y * (SS / KVP);
    const float* Kb = g_kh + (size_t)b * SS * DD + h * DKK;
    const float* Vb = g_vh + (size_t)b * SS * DD + h * DKK;

    __shared__ float ks[32][64];
    __shared__ float vs[32][64];

    int tid = threadIdx.x;
    int lrow = tid >> 3;
    int lcol = (tid & 7) << 3;
    int tj = (tid >> 4) << 2;
    int tk = (tid & 15) << 2;

    float acc[4][4];
    #pragma unroll
    for (int i = 0; i < 4; i++)
        #pragma unroll
        for (int j = 0; j < 4; j++) acc[i][j] = 0.0f;

    for (int s0 = s_base; s0 < s_base + SS / KVP; s0 += 32) {
        __syncthreads();
        const float* kp = Kb + (size_t)(s0 + lrow) * DD + lcol;
        const float* vp = Vb + (size_t)(s0 + lrow) * DD + lcol;
        *(float4*)&ks[lrow][lcol]     = *(const float4*)kp;
        *(float4*)&ks[lrow][lcol + 4] = *(const float4*)(kp + 4);
        *(float4*)&vs[lrow][lcol]     = *(const float4*)vp;
        *(float4*)&vs[lrow][lcol + 4] = *(const float4*)(vp + 4);
        __syncthreads();
        #pragma unroll
        for (int s = 0; s < 32; s++) {
            float4 kj4 = *(const float4*)&ks[s][tj];
            float4 vk4 = *(const float4*)&vs[s][tk];
            float kj[4] = {kj4.x, kj4.y, kj4.z, kj4.w};
            float vk[4] = {vk4.x, vk4.y, vk4.z, vk4.w};
            #pragma unroll
            for (int i = 0; i < 4; i++)
                #pragma unroll
                for (int j = 0; j < 4; j++)
                    acc[i][j] = fmaf(kj[i], vk[j], acc[i][j]);
        }
    }
    float* Mout = g_Mpart[bh * KVP + blockIdx.y];
    #pragma unroll
    for (int i = 0; i < 4; i++)
        #pragma unroll
        for (int j = 0; j < 4; j++)
            Mout[(tj + i) * DKK + tk + j] = acc[i][j];
}

__global__ __launch_bounds__(256) void reduce_M() {
    int bh = blockIdx.x;
    for (int e = threadIdx.x; e < DKK * DKK; e += 256) {
        float s = 0.0f;
        #pragma unroll
        for (int c = 0; c < KVP; c++) s += g_Mpart[bh * KVP + c][e];
        g_M[bh][e] = s;
    }
}

// ---------------------------------------------------------------------------
// heads = softmax_k( (Qh @ M) / 8 ), written as swizzled fp16 hi/lo panels
// ---------------------------------------------------------------------------
__global__ __launch_bounds__(256) void qm_softmax() {
    int bh = blockIdx.x;
    int b = bh >> 4, h = bh & 15;

    __shared__ float Ms[DKK * DKK];
    __shared__ float qs[8][DKK];

    int tid = threadIdx.x;
    const float4* Msrc = (const float4*)g_M[bh];
    for (int i = tid; i < (DKK * DKK) / 4; i += 256)
        ((float4*)Ms)[i] = Msrc[i];
    __syncthreads();

    int warp = tid >> 5, lane = tid & 31;
    int sbase = blockIdx.y * 128;

    for (int it = 0; it < 16; it++) {
        int s = sbase + (it << 3) + warp;
        const float* qrow = g_qh + ((size_t)(b * SS + s)) * DD + h * DKK;
        qs[warp][lane]      = qrow[lane];
        qs[warp][lane + 32] = qrow[lane + 32];
        __syncwarp();

        float o0 = 0.0f, o1 = 0.0f;
        #pragma unroll
        for (int j = 0; j < 64; j++) {
            float qv = qs[warp][j];
            o0 = fmaf(qv, Ms[(j << 6) + lane],      o0);
            o1 = fmaf(qv, Ms[(j << 6) + lane + 32], o1);
        }
        o0 *= 0.125f;
        o1 *= 0.125f;

        float mx = fmaxf(o0, o1);
        #pragma unroll
        for (int off = 16; off; off >>= 1)
            mx = fmaxf(mx, __shfl_xor_sync(0xffffffffu, mx, off));
        float e0 = __expf(o0 - mx), e1 = __expf(o1 - mx);
        float sm = e0 + e1;
        #pragma unroll
        for (int off = 16; off; off >>= 1)
            sm += __shfl_xor_sync(0xffffffffu, sm, off);
        float inv = 1.0f / sm;

        // write to fp16 128-row panel layout (pre-swizzled hi/lo)
        int mrow = b * SS + s;
        int mt = mrow >> 7, prow = mrow & 127;
        uint32_t off0 = (uint32_t)prow * 64 + lane * 2;
        uint32_t sw0 = sw64(off0) >> 1;
        size_t d0 = ((size_t)(mt * 32 + h * 2))     * ATILEH + sw0;
        size_t d1 = ((size_t)(mt * 32 + h * 2 + 1)) * ATILEH + sw0;
        float v0 = e0 * inv, v1 = e1 * inv;
        __half h0 = __float2half_rn(v0);
        __half h1 = __float2half_rn(v1);
        g_pan[3][0][d0] = h0;  g_pan[3][1][d0] = __float2half_rn(v0 - __half2float(h0));
        g_pan[3][0][d1] = h1;  g_pan[3][1][d1] = __float2half_rn(v1 - __half2float(h1));
        __syncwarp();
    }
}

// ---------------------------------------------------------------------------
extern "C" void kernel_launch(void* const* d_in, const int* in_sizes, int n_in,
                              void* d_out, int out_size) {
    const float* q    = (const float*)d_in[0];
    const float* k    = (const float*)d_in[1];
    const float* v    = (const float*)d_in[2];
    const float* wq_w = (const float*)d_in[3];
    const float* wq_b = (const float*)d_in[4];
    const float* wk_w = (const float*)d_in[5];
    const float* wk_b = (const float*)d_in[6];
    const float* wv_w = (const float*)d_in[7];
    const float* wv_b = (const float*)d_in[8];
    const float* wo_w = (const float*)d_in[9];
    const float* wo_b = (const float*)d_in[10];
    float* out = (float*)d_out;

    const int SMEM_BYTES = NSTG * CHB + 64;   // 147520
    cudaFuncSetAttribute(mma_gemm, cudaFuncAttributeMaxDynamicSharedMemorySize, SMEM_BYTES);

    prep_split<<<(DD * DD) / 256, 256>>>(wq_w, wk_w, wv_w, wo_w);
    split3<<<(MR * DD / 8) / 256, 256>>>(q, k, v);

    // fused QKV projection GEMMs: 3 widx x 4 nIdx
    mma_gemm<<<dim3(12, 64), 256, SMEM_BYTES>>>(wq_b, wk_b, wv_b, nullptr, nullptr, 0);

    kv_outer<<<dim3(BB * HH, KVP), 256>>>();
    reduce_M<<<BB * HH, 256>>>();
    qm_softmax<<<dim3(BB * HH, SS / 128), 256>>>();   // writes g_pan[3]

    // output projection
    mma_gemm<<<dim3(4, 64), 256, SMEM_BYTES>>>(nullptr, nullptr, nullptr, wo_b, out, 1);
}

// round 8
// speedup vs baseline: 1.0862x; 1.0862x over previous
#include <cuda_runtime.h>
#include <cuda_fp16.h>
#include <cstdint>

#define BB 4
#define SS 2048
#define DD 1024
#define HH 16
#define DKK 64
#define MR (BB*SS)   // 8192

#define MT 128
#define NT 128
#define NCH 32
#define TILEH 4096           // halves per 128x32 tile
#define TILEB 8192           // bytes per tile
#define CHB (4*TILEB)        // stage: Ahi|Alo|Bhi|Blo = 32KB
#define NSTG 3
#define KVP 16               // kv_outer partials

// ---------------- device scratch ----------------
__device__ __half g_wt[4][2][DD*DD];    // weight panels (x32 scaled, split hi/lo)
__device__ __half g_pan[4][2][MR*DD];   // activation panels: 0=q 1=k 2=v 3=softmax-out
__device__ float g_qh[MR*DD];
__device__ float g_kh[MR*DD];
__device__ float g_vh[MR*DD];
__device__ float g_Mpart[BB*HH*KVP][DKK*DKK];
__device__ float g_M[BB*HH][DKK*DKK];

// ---------------- helpers ----------------
__device__ __forceinline__ uint32_t smem_u32(const void* p) {
    uint32_t a;
    asm("{ .reg .u64 t; cvta.to.shared.u64 t, %1; cvt.u32.u64 %0, t; }" : "=r"(a) : "l"(p));
    return a;
}
#define MBAR_INIT(a, c) asm volatile("mbarrier.init.shared.b64 [%0], %1;" :: "r"(a), "r"(c) : "memory")
#define MBAR_WAIT(a, ph) do { \
    asm volatile("{\n\t.reg .pred P;\n\tWL%=:\n\t" \
        "mbarrier.try_wait.parity.shared.b64 P, [%0], %1;\n\t" \
        "@!P bra WL%=;\n\t}" :: "r"(a), "r"(ph) : "memory"); } while (0)
#define EXPECT_TX(a, n) asm volatile( \
    "mbarrier.arrive.expect_tx.shared.b64 _, [%0], %1;" :: "r"(a), "r"(n) : "memory")
#define BULK(dst, src, n, bar) asm volatile( \
    "cp.async.bulk.shared::cluster.global.mbarrier::complete_tx::bytes [%0], [%1], %2, [%3];" \
    :: "r"(dst), "l"(src), "r"(n), "r"(bar) : "memory")
#define LDSM4(r, a) asm volatile( \
    "ldmatrix.sync.aligned.m8n8.x4.shared.b16 {%0,%1,%2,%3}, [%4];" \
    : "=r"((r)[0]), "=r"((r)[1]), "=r"((r)[2]), "=r"((r)[3]) : "r"(a))
#define MMAF16(d, a, b0, b1) asm volatile( \
    "mma.sync.aligned.m16n8k16.row.col.f32.f16.f16.f32 " \
    "{%0,%1,%2,%3}, {%4,%5,%6,%7}, {%8,%9}, {%0,%1,%2,%3};" \
    : "+f"((d)[0]), "+f"((d)[1]), "+f"((d)[2]), "+f"((d)[3]) \
    : "r"((a)[0]), "r"((a)[1]), "r"((a)[2]), "r"((a)[3]), "r"(b0), "r"(b1))

// swizzle for 64B rows: XOR 16B-chunk index with row bits [1:2]
__device__ __forceinline__ uint32_t sw64(uint32_t off) {
    return off ^ ((off >> 3) & 0x30);
}

// ---------------------------------------------------------------------------
// fused prep: blocks [0, 4096) do weights; blocks [4096, 8192) do q/k/v split
// ---------------------------------------------------------------------------
__global__ void prep_all(const float* __restrict__ wq, const float* __restrict__ wk,
                         const float* __restrict__ wv, const float* __restrict__ wo,
                         const float* __restrict__ q, const float* __restrict__ k,
                         const float* __restrict__ v) {
    if (blockIdx.x < 4096) {
        // ---- weights: scale x32, split+transpose into pre-swizzled hi/lo panels ----
        int idx = blockIdx.x * 256 + threadIdx.x;      // n*1024 + kq
        int n = idx >> 10, kq = idx & 1023;
        int h = n >> 6, dk = n & 63;
        int src = h * (DD * DKK) + kq * DKK + dk;      // w[h][kq][dk]
        uint32_t off = (n & 127) * 64 + (kq & 31) * 2;
        size_t d = ((size_t)((n >> 7) * 32 + (kq >> 5))) * TILEH + (sw64(off) >> 1);
        float vals[4] = { wq[src] * 32.0f, wk[src] * 32.0f, wv[src] * 32.0f,
                          wo[n * DD + kq] * 32.0f };
        #pragma unroll
        for (int w = 0; w < 4; w++) {
            __half hi = __float2half_rn(vals[w]);
            __half lo = __float2half_rn(vals[w] - __half2float(hi));
            g_wt[w][0][d] = hi;
            g_wt[w][1][d] = lo;
        }
    } else {
        // ---- split q,k,v into pre-swizzled fp16 hi/lo panels ----
        int idx = (blockIdx.x - 4096) * 256 + threadIdx.x;  // chunk index (8 halves)
        int m = idx >> 7;
        int k0 = (idx & 127) << 3;
        uint32_t off = (m & 127) * 64 + (k0 & 31) * 2;
        size_t d = ((size_t)((m >> 7) * 32 + (k0 >> 5))) * TILEH + (sw64(off) >> 1);
        size_t s = (size_t)m * DD + k0;
        const float* srcs[3] = { q + s, k + s, v + s };
        #pragma unroll
        for (int w = 0; w < 3; w++) {
            float f[8];
            *(float4*)&f[0] = *(const float4*)(srcs[w]);
            *(float4*)&f[4] = *(const float4*)(srcs[w] + 4);
            __half hi[8], lo[8];
            #pragma unroll
            for (int i = 0; i < 8; i++) {
                hi[i] = __float2half_rn(f[i]);
                lo[i] = __float2half_rn(f[i] - __half2float(hi[i]));
            }
            *(uint4*)&g_pan[w][0][d] = *(uint4*)hi;
            *(uint4*)&g_pan[w][1][d] = *(uint4*)lo;
        }
    }
}

// ---------------------------------------------------------------------------
// 3x-split fp16 mma.sync GEMM, bulk-copy pipeline (R6 config).
// mode 0: fused QKV (grid.x=24 -> widx = x>>3), mode 1: wo (widx=3).
// ---------------------------------------------------------------------------
__global__ __launch_bounds__(256, 2) void mma_gemm(
        const float* __restrict__ b0p, const float* __restrict__ b1p,
        const float* __restrict__ b2p, const float* __restrict__ bwp,
        float* __restrict__ Oout, int mode) {
    extern __shared__ char smem[];
    int widx, nIdx;
    const float* bias;
    float* C;
    if (mode == 0) {
        widx = blockIdx.x >> 3;
        nIdx = blockIdx.x & 7;
        bias = (widx == 0) ? b0p : (widx == 1) ? b1p : b2p;
        C = (widx == 0) ? g_qh : (widx == 1) ? g_kh : g_vh;
    } else {
        widx = 3;
        nIdx = blockIdx.x;
        bias = bwp;
        C = Oout;
    }
    const __half* Ahi = g_pan[widx][0];
    const __half* Alo = g_pan[widx][1];
    const __half* Bhi = g_wt[widx][0];
    const __half* Blo = g_wt[widx][1];

    const uint32_t s0 = smem_u32(smem);
    const uint32_t mb = s0 + NSTG * CHB;

    const int tid = threadIdx.x;
    const int wid = tid >> 5, lane = tid & 31;
    const int bm = blockIdx.y * MT, bn = nIdx * NT;
    const int m0 = (wid >> 2) * 64;
    const int n0 = (wid & 3) * 32;

    if (tid == 0) { MBAR_INIT(mb, 1); MBAR_INIT(mb + 8, 1); MBAR_INIT(mb + 16, 1); }
    __syncthreads();

    auto issue = [&](int ch, int stg) {
        uint32_t sb = s0 + stg * CHB;
        uint32_t bar = mb + stg * 8;
        EXPECT_TX(bar, (uint32_t)CHB);
        const __half* a0 = Ahi + ((size_t)(blockIdx.y * 32 + ch)) * TILEH;
        const __half* a1 = Alo + ((size_t)(blockIdx.y * 32 + ch)) * TILEH;
        const __half* w0 = Bhi + ((size_t)(nIdx * 32 + ch)) * TILEH;
        const __half* w1 = Blo + ((size_t)(nIdx * 32 + ch)) * TILEH;
        BULK(sb,             a0, TILEB, bar);
        BULK(sb + TILEB,     a1, TILEB, bar);
        BULK(sb + 2 * TILEB, w0, TILEB, bar);
        BULK(sb + 3 * TILEB, w1, TILEB, bar);
    };
    if (tid == 0) { issue(0, 0); issue(1, 1); }

    // ldmatrix lane addressing (64B rows, sw64 swizzle)
    const int rowA = m0 + (lane & 7) + ((lane >> 3) & 1) * 8;
    const uint32_t cA = ((lane >> 4) & 1) * 16;
    const uint32_t xswA = (uint32_t)(rowA & 6) << 3;
    const uint32_t aRow = (uint32_t)rowA * 64;
    const int rowB = n0 + ((lane >> 4) << 3) + (lane & 7);
    const uint32_t cB = ((lane >> 3) & 1) * 16;
    const uint32_t xswB = (uint32_t)(rowB & 6) << 3;
    const uint32_t bRow = (uint32_t)rowB * 64;

    float acc[4][4][4];
    #pragma unroll
    for (int i = 0; i < 4; i++)
        #pragma unroll
        for (int j = 0; j < 4; j++)
            #pragma unroll
            for (int r = 0; r < 4; r++) acc[i][j][r] = 0.0f;

    for (int c = 0; c < NCH; ++c) {
        int stg = c % 3;
        uint32_t sb = s0 + stg * CHB;
        MBAR_WAIT(mb + stg * 8, (c / 3) & 1);

        #pragma unroll
        for (int ks = 0; ks < 2; ks++) {
            const uint32_t aoff = aRow + (((uint32_t)(ks * 32) + cA) ^ xswA);
            const uint32_t boff = bRow + (((uint32_t)(ks * 32) + cB) ^ xswB);
            uint32_t ah[4][4], al[4][4], bh[2][4], bl[2][4];
            // hi*hi
            #pragma unroll
            for (int i = 0; i < 4; i++) LDSM4(ah[i], sb + aoff + i * 1024);
            #pragma unroll
            for (int g = 0; g < 2; g++) LDSM4(bh[g], sb + 2 * TILEB + boff + g * 1024);
            #pragma unroll
            for (int i = 0; i < 4; i++) {
                MMAF16(acc[i][0], ah[i], bh[0][0], bh[0][1]);
                MMAF16(acc[i][1], ah[i], bh[0][2], bh[0][3]);
                MMAF16(acc[i][2], ah[i], bh[1][0], bh[1][1]);
                MMAF16(acc[i][3], ah[i], bh[1][2], bh[1][3]);
            }
            // hi*lo
            #pragma unroll
            for (int g = 0; g < 2; g++) LDSM4(bl[g], sb + 3 * TILEB + boff + g * 1024);
            #pragma unroll
            for (int i = 0; i < 4; i++) {
                MMAF16(acc[i][0], ah[i], bl[0][0], bl[0][1]);
                MMAF16(acc[i][1], ah[i], bl[0][2], bl[0][3]);
                MMAF16(acc[i][2], ah[i], bl[1][0], bl[1][1]);
                MMAF16(acc[i][3], ah[i], bl[1][2], bl[1][3]);
            }
            // lo*hi
            #pragma unroll
            for (int i = 0; i < 4; i++) LDSM4(al[i], sb + TILEB + aoff + i * 1024);
            #pragma unroll
            for (int i = 0; i < 4; i++) {
                MMAF16(acc[i][0], al[i], bh[0][0], bh[0][1]);
                MMAF16(acc[i][1], al[i], bh[0][2], bh[0][3]);
                MMAF16(acc[i][2], al[i], bh[1][0], bh[1][1]);
                MMAF16(acc[i][3], al[i], bh[1][2], bh[1][3]);
            }
        }
        __syncthreads();
        if (tid == 0 && c + 2 < NCH) issue(c + 2, (c + 2) % 3);
    }

    // ---- epilogue: undo x32 weight scale, add bias ----
    #pragma unroll
    for (int i = 0; i < 4; i++) {
        int row0 = bm + m0 + i * 16 + (lane >> 2);
        #pragma unroll
        for (int jj = 0; jj < 4; jj++) {
            int col = bn + n0 + jj * 8 + (lane & 3) * 2;
            float2 bv = *(const float2*)(bias + col);
            float2 r0, r1;
            r0.x = acc[i][jj][0] * 0.03125f + bv.x;  r0.y = acc[i][jj][1] * 0.03125f + bv.y;
            r1.x = acc[i][jj][2] * 0.03125f + bv.x;  r1.y = acc[i][jj][3] * 0.03125f + bv.y;
            *(float2*)(C + (size_t)row0 * DD + col) = r0;
            *(float2*)(C + (size_t)(row0 + 8) * DD + col) = r1;
        }
    }
}

// ---------------------------------------------------------------------------
// partial Kh^T @ Vh over 128-row s-chunks: grid (64, 16)
// ---------------------------------------------------------------------------
__global__ __launch_bounds__(256) void kv_outer() {
    int bh = blockIdx.x;
    int b = bh >> 4, h = bh & 15;
    int s_base = blockIdx.y * (SS / KVP);
    const float* Kb = g_kh + (size_t)b * SS * DD + h * DKK;
    const float* Vb = g_vh + (size_t)b * SS * DD + h * DKK;

    __shared__ float ks[32][64];
    __shared__ float vs[32][64];

    int tid = threadIdx.x;
    int lrow = tid >> 3;
    int lcol = (tid & 7) << 3;
    int tj = (tid >> 4) << 2;
    int tk = (tid & 15) << 2;

    float acc[4][4];
    #pragma unroll
    for (int i = 0; i < 4; i++)
        #pragma unroll
        for (int j = 0; j < 4; j++) acc[i][j] = 0.0f;

    for (int s0 = s_base; s0 < s_base + SS / KVP; s0 += 32) {
        __syncthreads();
        const float* kp = Kb + (size_t)(s0 + lrow) * DD + lcol;
        const float* vp = Vb + (size_t)(s0 + lrow) * DD + lcol;
        *(float4*)&ks[lrow][lcol]     = *(const float4*)kp;
        *(float4*)&ks[lrow][lcol + 4] = *(const float4*)(kp + 4);
        *(float4*)&vs[lrow][lcol]     = *(const float4*)vp;
        *(float4*)&vs[lrow][lcol + 4] = *(const float4*)(vp + 4);
        __syncthreads();
        #pragma unroll
        for (int s = 0; s < 32; s++) {
            float4 kj4 = *(const float4*)&ks[s][tj];
            float4 vk4 = *(const float4*)&vs[s][tk];
            float kj[4] = {kj4.x, kj4.y, kj4.z, kj4.w};
            float vk[4] = {vk4.x, vk4.y, vk4.z, vk4.w};
            #pragma unroll
            for (int i = 0; i < 4; i++)
                #pragma unroll
                for (int j = 0; j < 4; j++)
                    acc[i][j] = fmaf(kj[i], vk[j], acc[i][j]);
        }
    }
    float* Mout = g_Mpart[bh * KVP + blockIdx.y];
    #pragma unroll
    for (int i = 0; i < 4; i++)
        #pragma unroll
        for (int j = 0; j < 4; j++)
            Mout[(tj + i) * DKK + tk + j] = acc[i][j];
}

__global__ __launch_bounds__(256) void reduce_M() {
    int bh = blockIdx.x;
    for (int e = threadIdx.x; e < DKK * DKK; e += 256) {
        float s = 0.0f;
        #pragma unroll
        for (int c = 0; c < KVP; c++) s += g_Mpart[bh * KVP + c][e];
        g_M[bh][e] = s;
    }
}

// ---------------------------------------------------------------------------
// heads = softmax_k( (Qh @ M) / 8 ), written as swizzled fp16 hi/lo panels
// ---------------------------------------------------------------------------
__global__ __launch_bounds__(256) void qm_softmax() {
    int bh = blockIdx.x;
    int b = bh >> 4, h = bh & 15;

    __shared__ float Ms[DKK * DKK];
    __shared__ float qs[8][DKK];

    int tid = threadIdx.x;
    const float4* Msrc = (const float4*)g_M[bh];
    for (int i = tid; i < (DKK * DKK) / 4; i += 256)
        ((float4*)Ms)[i] = Msrc[i];
    __syncthreads();

    int warp = tid >> 5, lane = tid & 31;
    int sbase = blockIdx.y * 128;

    for (int it = 0; it < 16; it++) {
        int s = sbase + (it << 3) + warp;
        const float* qrow = g_qh + ((size_t)(b * SS + s)) * DD + h * DKK;
        qs[warp][lane]      = qrow[lane];
        qs[warp][lane + 32] = qrow[lane + 32];
        __syncwarp();

        float o0 = 0.0f, o1 = 0.0f;
        #pragma unroll
        for (int j = 0; j < 64; j++) {
            float qv = qs[warp][j];
            o0 = fmaf(qv, Ms[(j << 6) + lane],      o0);
            o1 = fmaf(qv, Ms[(j << 6) + lane + 32], o1);
        }
        o0 *= 0.125f;
        o1 *= 0.125f;

        float mx = fmaxf(o0, o1);
        #pragma unroll
        for (int off = 16; off; off >>= 1)
            mx = fmaxf(mx, __shfl_xor_sync(0xffffffffu, mx, off));
        float e0 = __expf(o0 - mx), e1 = __expf(o1 - mx);
        float sm = e0 + e1;
        #pragma unroll
        for (int off = 16; off; off >>= 1)
            sm += __shfl_xor_sync(0xffffffffu, sm, off);
        float inv = 1.0f / sm;

        // write to fp16 panel layout (pre-swizzled hi/lo)
        int mrow = b * SS + s;
        int mt = mrow >> 7, prow = mrow & 127;
        uint32_t off0 = (uint32_t)prow * 64 + lane * 2;
        uint32_t sw0 = sw64(off0) >> 1;
        size_t d0 = ((size_t)(mt * 32 + h * 2))     * TILEH + sw0;
        size_t d1 = ((size_t)(mt * 32 + h * 2 + 1)) * TILEH + sw0;
        float v0 = e0 * inv, v1 = e1 * inv;
        __half h0 = __float2half_rn(v0);
        __half h1 = __float2half_rn(v1);
        g_pan[3][0][d0] = h0;  g_pan[3][1][d0] = __float2half_rn(v0 - __half2float(h0));
        g_pan[3][0][d1] = h1;  g_pan[3][1][d1] = __float2half_rn(v1 - __half2float(h1));
        __syncwarp();
    }
}

// ---------------------------------------------------------------------------
extern "C" void kernel_launch(void* const* d_in, const int* in_sizes, int n_in,
                              void* d_out, int out_size) {
    const float* q    = (const float*)d_in[0];
    const float* k    = (const float*)d_in[1];
    const float* v    = (const float*)d_in[2];
    const float* wq_w = (const float*)d_in[3];
    const float* wq_b = (const float*)d_in[4];
    const float* wk_w = (const float*)d_in[5];
    const float* wk_b = (const float*)d_in[6];
    const float* wv_w = (const float*)d_in[7];
    const float* wv_b = (const float*)d_in[8];
    const float* wo_w = (const float*)d_in[9];
    const float* wo_b = (const float*)d_in[10];
    float* out = (float*)d_out;

    const int SMEM_BYTES = NSTG * CHB + 64;   // 98368
    cudaFuncSetAttribute(mma_gemm, cudaFuncAttributeMaxDynamicSharedMemorySize, SMEM_BYTES);

    // fused weight + activation prep (8192 blocks)
    prep_all<<<8192, 256>>>(wq_w, wk_w, wv_w, wo_w, q, k, v);

    // fused QKV projection GEMMs
    mma_gemm<<<dim3(24, 64), 256, SMEM_BYTES>>>(wq_b, wk_b, wv_b, nullptr, nullptr, 0);

    kv_outer<<<dim3(BB * HH, KVP), 256>>>();
    reduce_M<<<BB * HH, 256>>>();
    qm_softmax<<<dim3(BB * HH, SS / 128), 256>>>();   // writes g_pan[3]

    // output projection
    mma_gemm<<<dim3(8, 64), 256, SMEM_BYTES>>>(nullptr, nullptr, nullptr, wo_b, out, 1);
}

// round 9
// speedup vs baseline: 1.1091x; 1.0211x over previous
#include <cuda_runtime.h>
#include <cuda_fp16.h>
#include <cstdint>

#define BB 4
#define SS 2048
#define DD 1024
#define HH 16
#define DKK 64
#define MR (BB*SS)   // 8192

#define MT 128
#define NT 128
#define NCH 32
#define TILEH 4096           // halves per 128x32 tile
#define TILEB 8192           // bytes per tile
#define CHB (4*TILEB)        // stage: Ahi|Alo|Bhi|Blo = 32KB
#define NSTG 3
#define KVP 16               // kv_outer partials

// ---------------- device scratch ----------------
__device__ __half g_wt[4][2][DD*DD];    // weight panels (x32 scaled, split hi/lo)
__device__ __half g_pan[4][2][MR*DD];   // activation panels: 0=q 1=k 2=v 3=softmax-out
__device__ float g_qh[MR*DD];
__device__ float g_kh[MR*DD];
__device__ float g_vh[MR*DD];
__device__ float g_Mpart[BB*HH*KVP][DKK*DKK];
__device__ float g_M[BB*HH][DKK*DKK];

// ---------------- helpers ----------------
__device__ __forceinline__ uint32_t smem_u32(const void* p) {
    uint32_t a;
    asm("{ .reg .u64 t; cvta.to.shared.u64 t, %1; cvt.u32.u64 %0, t; }" : "=r"(a) : "l"(p));
    return a;
}
#define MBAR_INIT(a, c) asm volatile("mbarrier.init.shared.b64 [%0], %1;" :: "r"(a), "r"(c) : "memory")
#define MBAR_WAIT(a, ph) do { \
    asm volatile("{\n\t.reg .pred P;\n\tWL%=:\n\t" \
        "mbarrier.try_wait.parity.shared.b64 P, [%0], %1;\n\t" \
        "@!P bra WL%=;\n\t}" :: "r"(a), "r"(ph) : "memory"); } while (0)
#define EXPECT_TX(a, n) asm volatile( \
    "mbarrier.arrive.expect_tx.shared.b64 _, [%0], %1;" :: "r"(a), "r"(n) : "memory")
#define BULK(dst, src, n, bar) asm volatile( \
    "cp.async.bulk.shared::cluster.global.mbarrier::complete_tx::bytes [%0], [%1], %2, [%3];" \
    :: "r"(dst), "l"(src), "r"(n), "r"(bar) : "memory")
#define LDSM4(r, a) asm volatile( \
    "ldmatrix.sync.aligned.m8n8.x4.shared.b16 {%0,%1,%2,%3}, [%4];" \
    : "=r"((r)[0]), "=r"((r)[1]), "=r"((r)[2]), "=r"((r)[3]) : "r"(a))
#define MMAF16(d, a, b0, b1) asm volatile( \
    "mma.sync.aligned.m16n8k16.row.col.f32.f16.f16.f32 " \
    "{%0,%1,%2,%3}, {%4,%5,%6,%7}, {%8,%9}, {%0,%1,%2,%3};" \
    : "+f"((d)[0]), "+f"((d)[1]), "+f"((d)[2]), "+f"((d)[3]) \
    : "r"((a)[0]), "r"((a)[1]), "r"((a)[2]), "r"((a)[3]), "r"(b0), "r"(b1))

// swizzle for 64B rows: XOR 16B-chunk index with row bits [1:2]
__device__ __forceinline__ uint32_t sw64(uint32_t off) {
    return off ^ ((off >> 3) & 0x30);
}

// ---------------------------------------------------------------------------
// fused prep: blocks [0, 4096) do weights; blocks [4096, 8192) do q/k/v split
// ---------------------------------------------------------------------------
__global__ void prep_all(const float* __restrict__ wq, const float* __restrict__ wk,
                         const float* __restrict__ wv, const float* __restrict__ wo,
                         const float* __restrict__ q, const float* __restrict__ k,
                         const float* __restrict__ v) {
    if (blockIdx.x < 4096) {
        // ---- weights: scale x32, split+transpose into pre-swizzled hi/lo panels ----
        int idx = blockIdx.x * 256 + threadIdx.x;      // n*1024 + kq
        int n = idx >> 10, kq = idx & 1023;
        int h = n >> 6, dk = n & 63;
        int src = h * (DD * DKK) + kq * DKK + dk;      // w[h][kq][dk]
        uint32_t off = (n & 127) * 64 + (kq & 31) * 2;
        size_t d = ((size_t)((n >> 7) * 32 + (kq >> 5))) * TILEH + (sw64(off) >> 1);
        float vals[4] = { wq[src] * 32.0f, wk[src] * 32.0f, wv[src] * 32.0f,
                          wo[n * DD + kq] * 32.0f };
        #pragma unroll
        for (int w = 0; w < 4; w++) {
            __half hi = __float2half_rn(vals[w]);
            __half lo = __float2half_rn(vals[w] - __half2float(hi));
            g_wt[w][0][d] = hi;
            g_wt[w][1][d] = lo;
        }
    } else {
        // ---- split q,k,v into pre-swizzled fp16 hi/lo panels ----
        int idx = (blockIdx.x - 4096) * 256 + threadIdx.x;  // chunk index (8 halves)
        int m = idx >> 7;
        int k0 = (idx & 127) << 3;
        uint32_t off = (m & 127) * 64 + (k0 & 31) * 2;
        size_t d = ((size_t)((m >> 7) * 32 + (k0 >> 5))) * TILEH + (sw64(off) >> 1);
        size_t s = (size_t)m * DD + k0;
        const float* srcs[3] = { q + s, k + s, v + s };
        #pragma unroll
        for (int w = 0; w < 3; w++) {
            float f[8];
            *(float4*)&f[0] = *(const float4*)(srcs[w]);
            *(float4*)&f[4] = *(const float4*)(srcs[w] + 4);
            __half hi[8], lo[8];
            #pragma unroll
            for (int i = 0; i < 8; i++) {
                hi[i] = __float2half_rn(f[i]);
                lo[i] = __float2half_rn(f[i] - __half2float(hi[i]));
            }
            *(uint4*)&g_pan[w][0][d] = *(uint4*)hi;
            *(uint4*)&g_pan[w][1][d] = *(uint4*)lo;
        }
    }
}

// ---------------------------------------------------------------------------
// 3x-split fp16 mma.sync GEMM, bulk-copy pipeline, issue-at-top (3-deep).
// mode 0: fused QKV (grid.x=24 -> widx = x>>3), mode 1: wo (widx=3).
// ---------------------------------------------------------------------------
__global__ __launch_bounds__(256, 2) void mma_gemm(
        const float* __restrict__ b0p, const float* __restrict__ b1p,
        const float* __restrict__ b2p, const float* __restrict__ bwp,
        float* __restrict__ Oout, int mode) {
    extern __shared__ char smem[];
    int widx, nIdx;
    const float* bias;
    float* C;
    if (mode == 0) {
        widx = blockIdx.x >> 3;
        nIdx = blockIdx.x & 7;
        bias = (widx == 0) ? b0p : (widx == 1) ? b1p : b2p;
        C = (widx == 0) ? g_qh : (widx == 1) ? g_kh : g_vh;
    } else {
        widx = 3;
        nIdx = blockIdx.x;
        bias = bwp;
        C = Oout;
    }
    const __half* Ahi = g_pan[widx][0];
    const __half* Alo = g_pan[widx][1];
    const __half* Bhi = g_wt[widx][0];
    const __half* Blo = g_wt[widx][1];

    const uint32_t s0 = smem_u32(smem);
    const uint32_t mb = s0 + NSTG * CHB;

    const int tid = threadIdx.x;
    const int wid = tid >> 5, lane = tid & 31;
    const int bm = blockIdx.y * MT, bn = nIdx * NT;
    const int m0 = (wid >> 2) * 64;
    const int n0 = (wid & 3) * 32;

    if (tid == 0) { MBAR_INIT(mb, 1); MBAR_INIT(mb + 8, 1); MBAR_INIT(mb + 16, 1); }
    __syncthreads();

    auto issue = [&](int ch, int stg) {
        uint32_t sb = s0 + stg * CHB;
        uint32_t bar = mb + stg * 8;
        EXPECT_TX(bar, (uint32_t)CHB);
        const __half* a0 = Ahi + ((size_t)(blockIdx.y * 32 + ch)) * TILEH;
        const __half* a1 = Alo + ((size_t)(blockIdx.y * 32 + ch)) * TILEH;
        const __half* w0 = Bhi + ((size_t)(nIdx * 32 + ch)) * TILEH;
        const __half* w1 = Blo + ((size_t)(nIdx * 32 + ch)) * TILEH;
        BULK(sb,             a0, TILEB, bar);
        BULK(sb + TILEB,     a1, TILEB, bar);
        BULK(sb + 2 * TILEB, w0, TILEB, bar);
        BULK(sb + 3 * TILEB, w1, TILEB, bar);
    };
    if (tid == 0) { issue(0, 0); issue(1, 1); }

    // ldmatrix lane addressing (64B rows, sw64 swizzle)
    const int rowA = m0 + (lane & 7) + ((lane >> 3) & 1) * 8;
    const uint32_t cA = ((lane >> 4) & 1) * 16;
    const uint32_t xswA = (uint32_t)(rowA & 6) << 3;
    const uint32_t aRow = (uint32_t)rowA * 64;
    const int rowB = n0 + ((lane >> 4) << 3) + (lane & 7);
    const uint32_t cB = ((lane >> 3) & 1) * 16;
    const uint32_t xswB = (uint32_t)(rowB & 6) << 3;
    const uint32_t bRow = (uint32_t)rowB * 64;

    float acc[4][4][4];
    #pragma unroll
    for (int i = 0; i < 4; i++)
        #pragma unroll
        for (int j = 0; j < 4; j++)
            #pragma unroll
            for (int r = 0; r < 4; r++) acc[i][j][r] = 0.0f;

    for (int c = 0; c < NCH; ++c) {
        int stg = c % 3;
        uint32_t sb = s0 + stg * CHB;
        MBAR_WAIT(mb + stg * 8, (c / 3) & 1);
        // stage (c+2)%3 was freed at end of chunk c-1 (syncthreads) -> issue NOW,
        // before compute, keeping 3 chunks in flight.
        if (tid == 0 && c + 2 < NCH) issue(c + 2, (c + 2) % 3);

        #pragma unroll
        for (int ks = 0; ks < 2; ks++) {
            const uint32_t aoff = aRow + (((uint32_t)(ks * 32) + cA) ^ xswA);
            const uint32_t boff = bRow + (((uint32_t)(ks * 32) + cB) ^ xswB);
            uint32_t ah[4][4], al[4][4], bh[2][4], bl[2][4];
            // hi*hi
            #pragma unroll
            for (int i = 0; i < 4; i++) LDSM4(ah[i], sb + aoff + i * 1024);
            #pragma unroll
            for (int g = 0; g < 2; g++) LDSM4(bh[g], sb + 2 * TILEB + boff + g * 1024);
            #pragma unroll
            for (int i = 0; i < 4; i++) {
                MMAF16(acc[i][0], ah[i], bh[0][0], bh[0][1]);
                MMAF16(acc[i][1], ah[i], bh[0][2], bh[0][3]);
                MMAF16(acc[i][2], ah[i], bh[1][0], bh[1][1]);
                MMAF16(acc[i][3], ah[i], bh[1][2], bh[1][3]);
            }
            // hi*lo
            #pragma unroll
            for (int g = 0; g < 2; g++) LDSM4(bl[g], sb + 3 * TILEB + boff + g * 1024);
            #pragma unroll
            for (int i = 0; i < 4; i++) {
                MMAF16(acc[i][0], ah[i], bl[0][0], bl[0][1]);
                MMAF16(acc[i][1], ah[i], bl[0][2], bl[0][3]);
                MMAF16(acc[i][2], ah[i], bl[1][0], bl[1][1]);
                MMAF16(acc[i][3], ah[i], bl[1][2], bl[1][3]);
            }
            // lo*hi
            #pragma unroll
            for (int i = 0; i < 4; i++) LDSM4(al[i], sb + TILEB + aoff + i * 1024);
            #pragma unroll
            for (int i = 0; i < 4; i++) {
                MMAF16(acc[i][0], al[i], bh[0][0], bh[0][1]);
                MMAF16(acc[i][1], al[i], bh[0][2], bh[0][3]);
                MMAF16(acc[i][2], al[i], bh[1][0], bh[1][1]);
                MMAF16(acc[i][3], al[i], bh[1][2], bh[1][3]);
            }
        }
        __syncthreads();
    }

    // ---- epilogue: undo x32 weight scale, add bias ----
    #pragma unroll
    for (int i = 0; i < 4; i++) {
        int row0 = bm + m0 + i * 16 + (lane >> 2);
        #pragma unroll
        for (int jj = 0; jj < 4; jj++) {
            int col = bn + n0 + jj * 8 + (lane & 3) * 2;
            float2 bv = *(const float2*)(bias + col);
            float2 r0, r1;
            r0.x = acc[i][jj][0] * 0.03125f + bv.x;  r0.y = acc[i][jj][1] * 0.03125f + bv.y;
            r1.x = acc[i][jj][2] * 0.03125f + bv.x;  r1.y = acc[i][jj][3] * 0.03125f + bv.y;
            *(float2*)(C + (size_t)row0 * DD + col) = r0;
            *(float2*)(C + (size_t)(row0 + 8) * DD + col) = r1;
        }
    }
}

// ---------------------------------------------------------------------------
// partial Kh^T @ Vh over 128-row s-chunks: grid (64, 16)
// ---------------------------------------------------------------------------
__global__ __launch_bounds__(256) void kv_outer() {
    int bh = blockIdx.x;
    int b = bh >> 4, h = bh & 15;
    int s_base = blockIdx.y * (SS / KVP);
    const float* Kb = g_kh + (size_t)b * SS * DD + h * DKK;
    const float* Vb = g_vh + (size_t)b * SS * DD + h * DKK;

    __shared__ float ks[32][64];
    __shared__ float vs[32][64];

    int tid = threadIdx.x;
    int lrow = tid >> 3;
    int lcol = (tid & 7) << 3;
    int tj = (tid >> 4) << 2;
    int tk = (tid & 15) << 2;

    float acc[4][4];
    #pragma unroll
    for (int i = 0; i < 4; i++)
        #pragma unroll
        for (int j = 0; j < 4; j++) acc[i][j] = 0.0f;

    for (int s0 = s_base; s0 < s_base + SS / KVP; s0 += 32) {
        __syncthreads();
        const float* kp = Kb + (size_t)(s0 + lrow) * DD + lcol;
        const float* vp = Vb + (size_t)(s0 + lrow) * DD + lcol;
        *(float4*)&ks[lrow][lcol]     = *(const float4*)kp;
        *(float4*)&ks[lrow][lcol + 4] = *(const float4*)(kp + 4);
        *(float4*)&vs[lrow][lcol]     = *(const float4*)vp;
        *(float4*)&vs[lrow][lcol + 4] = *(const float4*)(vp + 4);
        __syncthreads();
        #pragma unroll
        for (int s = 0; s < 32; s++) {
            float4 kj4 = *(const float4*)&ks[s][tj];
            float4 vk4 = *(const float4*)&vs[s][tk];
            float kj[4] = {kj4.x, kj4.y, kj4.z, kj4.w};
            float vk[4] = {vk4.x, vk4.y, vk4.z, vk4.w};
            #pragma unroll
            for (int i = 0; i < 4; i++)
                #pragma unroll
                for (int j = 0; j < 4; j++)
                    acc[i][j] = fmaf(kj[i], vk[j], acc[i][j]);
        }
    }
    float* Mout = g_Mpart[bh * KVP + blockIdx.y];
    #pragma unroll
    for (int i = 0; i < 4; i++)
        #pragma unroll
        for (int j = 0; j < 4; j++)
            Mout[(tj + i) * DKK + tk + j] = acc[i][j];
}

// flat 256-block reduce: one float4 output per thread
__global__ __launch_bounds__(256) void reduce_M() {
    int t = blockIdx.x * 256 + threadIdx.x;      // 0 .. 65535 float4 outputs
    int bh = t >> 10;                            // 1024 float4 per bh
    int e4 = t & 1023;
    float4 s = make_float4(0.f, 0.f, 0.f, 0.f);
    #pragma unroll
    for (int c = 0; c < KVP; c++) {
        float4 p = *(const float4*)&g_Mpart[bh * KVP + c][e4 * 4];
        s.x += p.x; s.y += p.y; s.z += p.z; s.w += p.w;
    }
    *(float4*)&g_M[bh][e4 * 4] = s;
}

// ---------------------------------------------------------------------------
// heads = softmax_k( (Qh @ M) / 8 ), written as swizzled fp16 hi/lo panels
// ---------------------------------------------------------------------------
__global__ __launch_bounds__(256) void qm_softmax() {
    int bh = blockIdx.x;
    int b = bh >> 4, h = bh & 15;

    __shared__ float Ms[DKK * DKK];
    __shared__ float qs[8][DKK];

    int tid = threadIdx.x;
    const float4* Msrc = (const float4*)g_M[bh];
    for (int i = tid; i < (DKK * DKK) / 4; i += 256)
        ((float4*)Ms)[i] = Msrc[i];
    __syncthreads();

    int warp = tid >> 5, lane = tid & 31;
    int sbase = blockIdx.y * 128;

    for (int it = 0; it < 16; it++) {
        int s = sbase + (it << 3) + warp;
        const float* qrow = g_qh + ((size_t)(b * SS + s)) * DD + h * DKK;
        qs[warp][lane]      = qrow[lane];
        qs[warp][lane + 32] = qrow[lane + 32];
        __syncwarp();

        float o0 = 0.0f, o1 = 0.0f;
        #pragma unroll
        for (int j = 0; j < 64; j++) {
            float qv = qs[warp][j];
            o0 = fmaf(qv, Ms[(j << 6) + lane],      o0);
            o1 = fmaf(qv, Ms[(j << 6) + lane + 32], o1);
        }
        o0 *= 0.125f;
        o1 *= 0.125f;

        float mx = fmaxf(o0, o1);
        #pragma unroll
        for (int off = 16; off; off >>= 1)
            mx = fmaxf(mx, __shfl_xor_sync(0xffffffffu, mx, off));
        float e0 = __expf(o0 - mx), e1 = __expf(o1 - mx);
        float sm = e0 + e1;
        #pragma unroll
        for (int off = 16; off; off >>= 1)
            sm += __shfl_xor_sync(0xffffffffu, sm, off);
        float inv = 1.0f / sm;

        // write to fp16 panel layout (pre-swizzled hi/lo)
        int mrow = b * SS + s;
        int mt = mrow >> 7, prow = mrow & 127;
        uint32_t off0 = (uint32_t)prow * 64 + lane * 2;
        uint32_t sw0 = sw64(off0) >> 1;
        size_t d0 = ((size_t)(mt * 32 + h * 2))     * TILEH + sw0;
        size_t d1 = ((size_t)(mt * 32 + h * 2 + 1)) * TILEH + sw0;
        float v0 = e0 * inv, v1 = e1 * inv;
        __half h0 = __float2half_rn(v0);
        __half h1 = __float2half_rn(v1);
        g_pan[3][0][d0] = h0;  g_pan[3][1][d0] = __float2half_rn(v0 - __half2float(h0));
        g_pan[3][0][d1] = h1;  g_pan[3][1][d1] = __float2half_rn(v1 - __half2float(h1));
        __syncwarp();
    }
}

// ---------------------------------------------------------------------------
extern "C" void kernel_launch(void* const* d_in, const int* in_sizes, int n_in,
                              void* d_out, int out_size) {
    const float* q    = (const float*)d_in[0];
    const float* k    = (const float*)d_in[1];
    const float* v    = (const float*)d_in[2];
    const float* wq_w = (const float*)d_in[3];
    const float* wq_b = (const float*)d_in[4];
    const float* wk_w = (const float*)d_in[5];
    const float* wk_b = (const float*)d_in[6];
    const float* wv_w = (const float*)d_in[7];
    const float* wv_b = (const float*)d_in[8];
    const float* wo_w = (const float*)d_in[9];
    const float* wo_b = (const float*)d_in[10];
    float* out = (float*)d_out;

    const int SMEM_BYTES = NSTG * CHB + 64;   // 98368
    cudaFuncSetAttribute(mma_gemm, cudaFuncAttributeMaxDynamicSharedMemorySize, SMEM_BYTES);

    // fused weight + activation prep (8192 blocks)
    prep_all<<<8192, 256>>>(wq_w, wk_w, wv_w, wo_w, q, k, v);

    // fused QKV projection GEMMs
    mma_gemm<<<dim3(24, 64), 256, SMEM_BYTES>>>(wq_b, wk_b, wv_b, nullptr, nullptr, 0);

    kv_outer<<<dim3(BB * HH, KVP), 256>>>();
    reduce_M<<<256, 256>>>();
    qm_softmax<<<dim3(BB * HH, SS / 128), 256>>>();   // writes g_pan[3]

    // output projection
    mma_gemm<<<dim3(8, 64), 256, SMEM_BYTES>>>(nullptr, nullptr, nullptr, wo_b, out, 1);
}

// round 10
// speedup vs baseline: 1.1661x; 1.0514x over previous
#include <cuda_runtime.h>
#include <cuda_fp16.h>
#include <cstdint>

#define BB 4
#define SS 2048
#define DD 1024
#define HH 16
#define DKK 64
#define MR (BB*SS)   // 8192

#define MT 128
#define NT 128
#define NCH 32
#define TILEH 4096           // halves per 128x32 tile
#define TILEB 8192           // bytes per tile
#define CHB (4*TILEB)        // stage: Ahi|Alo|Bhi|Blo = 32KB
#define NSTG 3
#define KVP 16               // kv_outer partials

// ---------------- device scratch ----------------
__device__ __half g_wt[4][2][DD*DD];    // weight panels (x32 scaled, split hi/lo)
__device__ __half g_pan[4][2][MR*DD];   // activation panels: 0=q 1=k 2=v 3=softmax-out
__device__ float g_qh[MR*DD];
__device__ float g_kh[MR*DD];
__device__ float g_vh[MR*DD];
__device__ float g_Mpart[BB*HH*KVP][DKK*DKK];
__device__ float g_M[BB*HH][DKK*DKK];

// ---------------- helpers ----------------
__device__ __forceinline__ uint32_t smem_u32(const void* p) {
    uint32_t a;
    asm("{ .reg .u64 t; cvta.to.shared.u64 t, %1; cvt.u32.u64 %0, t; }" : "=r"(a) : "l"(p));
    return a;
}
#define MBAR_INIT(a, c) asm volatile("mbarrier.init.shared.b64 [%0], %1;" :: "r"(a), "r"(c) : "memory")
#define MBAR_WAIT(a, ph) do { \
    asm volatile("{\n\t.reg .pred P;\n\tWL%=:\n\t" \
        "mbarrier.try_wait.parity.shared.b64 P, [%0], %1;\n\t" \
        "@!P bra WL%=;\n\t}" :: "r"(a), "r"(ph) : "memory"); } while (0)
#define EXPECT_TX(a, n) asm volatile( \
    "mbarrier.arrive.expect_tx.shared.b64 _, [%0], %1;" :: "r"(a), "r"(n) : "memory")
#define BULK(dst, src, n, bar) asm volatile( \
    "cp.async.bulk.shared::cluster.global.mbarrier::complete_tx::bytes [%0], [%1], %2, [%3];" \
    :: "r"(dst), "l"(src), "r"(n), "r"(bar) : "memory")
#define LDSM4(r, a) asm volatile( \
    "ldmatrix.sync.aligned.m8n8.x4.shared.b16 {%0,%1,%2,%3}, [%4];" \
    : "=r"((r)[0]), "=r"((r)[1]), "=r"((r)[2]), "=r"((r)[3]) : "r"(a))
#define MMAF16(d, a, b0, b1) asm volatile( \
    "mma.sync.aligned.m16n8k16.row.col.f32.f16.f16.f32 " \
    "{%0,%1,%2,%3}, {%4,%5,%6,%7}, {%8,%9}, {%0,%1,%2,%3};" \
    : "+f"((d)[0]), "+f"((d)[1]), "+f"((d)[2]), "+f"((d)[3]) \
    : "r"((a)[0]), "r"((a)[1]), "r"((a)[2]), "r"((a)[3]), "r"(b0), "r"(b1))

// swizzle for 64B rows: XOR 16B-chunk index with row bits [1:2]
__device__ __forceinline__ uint32_t sw64(uint32_t off) {
    return off ^ ((off >> 3) & 0x30);
}

// ---------------------------------------------------------------------------
// fused prep: blocks [0, 4096) do weights; blocks [4096, 8192) do q/k/v split
// ---------------------------------------------------------------------------
__global__ void prep_all(const float* __restrict__ wq, const float* __restrict__ wk,
                         const float* __restrict__ wv, const float* __restrict__ wo,
                         const float* __restrict__ q, const float* __restrict__ k,
                         const float* __restrict__ v) {
    if (blockIdx.x < 4096) {
        // ---- weights: scale x32, split+transpose into pre-swizzled hi/lo panels ----
        int idx = blockIdx.x * 256 + threadIdx.x;      // n*1024 + kq
        int n = idx >> 10, kq = idx & 1023;
        int h = n >> 6, dk = n & 63;
        int src = h * (DD * DKK) + kq * DKK + dk;      // w[h][kq][dk]
        uint32_t off = (n & 127) * 64 + (kq & 31) * 2;
        size_t d = ((size_t)((n >> 7) * 32 + (kq >> 5))) * TILEH + (sw64(off) >> 1);
        float vals[4] = { wq[src] * 32.0f, wk[src] * 32.0f, wv[src] * 32.0f,
                          wo[n * DD + kq] * 32.0f };
        #pragma unroll
        for (int w = 0; w < 4; w++) {
            __half hi = __float2half_rn(vals[w]);
            __half lo = __float2half_rn(vals[w] - __half2float(hi));
            g_wt[w][0][d] = hi;
            g_wt[w][1][d] = lo;
        }
    } else {
        // ---- split q,k,v into pre-swizzled fp16 hi/lo panels ----
        int idx = (blockIdx.x - 4096) * 256 + threadIdx.x;  // chunk index (8 halves)
        int m = idx >> 7;
        int k0 = (idx & 127) << 3;
        uint32_t off = (m & 127) * 64 + (k0 & 31) * 2;
        size_t d = ((size_t)((m >> 7) * 32 + (k0 >> 5))) * TILEH + (sw64(off) >> 1);
        size_t s = (size_t)m * DD + k0;
        const float* srcs[3] = { q + s, k + s, v + s };
        #pragma unroll
        for (int w = 0; w < 3; w++) {
            float f[8];
            *(float4*)&f[0] = *(const float4*)(srcs[w]);
            *(float4*)&f[4] = *(const float4*)(srcs[w] + 4);
            __half hi[8], lo[8];
            #pragma unroll
            for (int i = 0; i < 8; i++) {
                hi[i] = __float2half_rn(f[i]);
                lo[i] = __float2half_rn(f[i] - __half2float(hi[i]));
            }
            *(uint4*)&g_pan[w][0][d] = *(uint4*)hi;
            *(uint4*)&g_pan[w][1][d] = *(uint4*)lo;
        }
    }
}

// ---------------------------------------------------------------------------
// split fp16 mma.sync GEMM, bulk-copy pipeline, issue-at-top (3-deep).
// mode 0: fused QKV, 3-pass split (grid.x=24 -> widx = x>>3)
// mode 1: wo, 2-pass split (A_lo dropped; A = softmax probs, no amplification)
// ---------------------------------------------------------------------------
__global__ __launch_bounds__(256, 2) void mma_gemm(
        const float* __restrict__ b0p, const float* __restrict__ b1p,
        const float* __restrict__ b2p, const float* __restrict__ bwp,
        float* __restrict__ Oout, int mode) {
    extern __shared__ char smem[];
    int widx, nIdx;
    const float* bias;
    float* C;
    if (mode == 0) {
        widx = blockIdx.x >> 3;
        nIdx = blockIdx.x & 7;
        bias = (widx == 0) ? b0p : (widx == 1) ? b1p : b2p;
        C = (widx == 0) ? g_qh : (widx == 1) ? g_kh : g_vh;
    } else {
        widx = 3;
        nIdx = blockIdx.x;
        bias = bwp;
        C = Oout;
    }
    const __half* Ahi = g_pan[widx][0];
    const __half* Alo = g_pan[widx][1];
    const __half* Bhi = g_wt[widx][0];
    const __half* Blo = g_wt[widx][1];

    const uint32_t s0 = smem_u32(smem);
    const uint32_t mb = s0 + NSTG * CHB;

    const int tid = threadIdx.x;
    const int wid = tid >> 5, lane = tid & 31;
    const int bm = blockIdx.y * MT, bn = nIdx * NT;
    const int m0 = (wid >> 2) * 64;
    const int n0 = (wid & 3) * 32;

    if (tid == 0) { MBAR_INIT(mb, 1); MBAR_INIT(mb + 8, 1); MBAR_INIT(mb + 16, 1); }
    __syncthreads();

    const uint32_t stage_bytes = (mode == 0) ? 4u * TILEB : 3u * TILEB;
    auto issue = [&](int ch, int stg) {
        uint32_t sb = s0 + stg * CHB;
        uint32_t bar = mb + stg * 8;
        EXPECT_TX(bar, stage_bytes);
        const __half* a0 = Ahi + ((size_t)(blockIdx.y * 32 + ch)) * TILEH;
        const __half* w0 = Bhi + ((size_t)(nIdx * 32 + ch)) * TILEH;
        const __half* w1 = Blo + ((size_t)(nIdx * 32 + ch)) * TILEH;
        BULK(sb,             a0, TILEB, bar);
        if (mode == 0) {
            const __half* a1 = Alo + ((size_t)(blockIdx.y * 32 + ch)) * TILEH;
            BULK(sb + TILEB, a1, TILEB, bar);
        }
        BULK(sb + 2 * TILEB, w0, TILEB, bar);
        BULK(sb + 3 * TILEB, w1, TILEB, bar);
    };
    if (tid == 0) { issue(0, 0); issue(1, 1); }

    // ldmatrix lane addressing (64B rows, sw64 swizzle)
    const int rowA = m0 + (lane & 7) + ((lane >> 3) & 1) * 8;
    const uint32_t cA = ((lane >> 4) & 1) * 16;
    const uint32_t xswA = (uint32_t)(rowA & 6) << 3;
    const uint32_t aRow = (uint32_t)rowA * 64;
    const int rowB = n0 + ((lane >> 4) << 3) + (lane & 7);
    const uint32_t cB = ((lane >> 3) & 1) * 16;
    const uint32_t xswB = (uint32_t)(rowB & 6) << 3;
    const uint32_t bRow = (uint32_t)rowB * 64;

    float acc[4][4][4];
    #pragma unroll
    for (int i = 0; i < 4; i++)
        #pragma unroll
        for (int j = 0; j < 4; j++)
            #pragma unroll
            for (int r = 0; r < 4; r++) acc[i][j][r] = 0.0f;

    for (int c = 0; c < NCH; ++c) {
        int stg = c % 3;
        uint32_t sb = s0 + stg * CHB;
        MBAR_WAIT(mb + stg * 8, (c / 3) & 1);
        // stage (c+2)%3 freed at end of chunk c-1 -> issue NOW, before compute.
        if (tid == 0 && c + 2 < NCH) issue(c + 2, (c + 2) % 3);

        #pragma unroll
        for (int ks = 0; ks < 2; ks++) {
            const uint32_t aoff = aRow + (((uint32_t)(ks * 32) + cA) ^ xswA);
            const uint32_t boff = bRow + (((uint32_t)(ks * 32) + cB) ^ xswB);
            uint32_t ah[4][4], al[4][4], bh[2][4], bl[2][4];
            // hi*hi
            #pragma unroll
            for (int i = 0; i < 4; i++) LDSM4(ah[i], sb + aoff + i * 1024);
            #pragma unroll
            for (int g = 0; g < 2; g++) LDSM4(bh[g], sb + 2 * TILEB + boff + g * 1024);
            #pragma unroll
            for (int i = 0; i < 4; i++) {
                MMAF16(acc[i][0], ah[i], bh[0][0], bh[0][1]);
                MMAF16(acc[i][1], ah[i], bh[0][2], bh[0][3]);
                MMAF16(acc[i][2], ah[i], bh[1][0], bh[1][1]);
                MMAF16(acc[i][3], ah[i], bh[1][2], bh[1][3]);
            }
            // hi*lo
            #pragma unroll
            for (int g = 0; g < 2; g++) LDSM4(bl[g], sb + 3 * TILEB + boff + g * 1024);
            #pragma unroll
            for (int i = 0; i < 4; i++) {
                MMAF16(acc[i][0], ah[i], bl[0][0], bl[0][1]);
                MMAF16(acc[i][1], ah[i], bl[0][2], bl[0][3]);
                MMAF16(acc[i][2], ah[i], bl[1][0], bl[1][1]);
                MMAF16(acc[i][3], ah[i], bl[1][2], bl[1][3]);
            }
            // lo*hi (QKV only — softmax-output GEMM tolerates dropping A_lo)
            if (mode == 0) {
                #pragma unroll
                for (int i = 0; i < 4; i++) LDSM4(al[i], sb + TILEB + aoff + i * 1024);
                #pragma unroll
                for (int i = 0; i < 4; i++) {
                    MMAF16(acc[i][0], al[i], bh[0][0], bh[0][1]);
                    MMAF16(acc[i][1], al[i], bh[0][2], bh[0][3]);
                    MMAF16(acc[i][2], al[i], bh[1][0], bh[1][1]);
                    MMAF16(acc[i][3], al[i], bh[1][2], bh[1][3]);
                }
            }
        }
        __syncthreads();
    }

    // ---- epilogue: undo x32 weight scale, add bias ----
    #pragma unroll
    for (int i = 0; i < 4; i++) {
        int row0 = bm + m0 + i * 16 + (lane >> 2);
        #pragma unroll
        for (int jj = 0; jj < 4; jj++) {
            int col = bn + n0 + jj * 8 + (lane & 3) * 2;
            float2 bv = *(const float2*)(bias + col);
            float2 r0, r1;
            r0.x = acc[i][jj][0] * 0.03125f + bv.x;  r0.y = acc[i][jj][1] * 0.03125f + bv.y;
            r1.x = acc[i][jj][2] * 0.03125f + bv.x;  r1.y = acc[i][jj][3] * 0.03125f + bv.y;
            *(float2*)(C + (size_t)row0 * DD + col) = r0;
            *(float2*)(C + (size_t)(row0 + 8) * DD + col) = r1;
        }
    }
}

// ---------------------------------------------------------------------------
// partial Kh^T @ Vh over 128-row s-chunks: grid (64, 16)
// ---------------------------------------------------------------------------
__global__ __launch_bounds__(256) void kv_outer() {
    int bh = blockIdx.x;
    int b = bh >> 4, h = bh & 15;
    int s_base = blockIdx.y * (SS / KVP);
    const float* Kb = g_kh + (size_t)b * SS * DD + h * DKK;
    const float* Vb = g_vh + (size_t)b * SS * DD + h * DKK;

    __shared__ float ks[32][64];
    __shared__ float vs[32][64];

    int tid = threadIdx.x;
    int lrow = tid >> 3;
    int lcol = (tid & 7) << 3;
    int tj = (tid >> 4) << 2;
    int tk = (tid & 15) << 2;

    float acc[4][4];
    #pragma unroll
    for (int i = 0; i < 4; i++)
        #pragma unroll
        for (int j = 0; j < 4; j++) acc[i][j] = 0.0f;

    for (int s0 = s_base; s0 < s_base + SS / KVP; s0 += 32) {
        __syncthreads();
        const float* kp = Kb + (size_t)(s0 + lrow) * DD + lcol;
        const float* vp = Vb + (size_t)(s0 + lrow) * DD + lcol;
        *(float4*)&ks[lrow][lcol]     = *(const float4*)kp;
        *(float4*)&ks[lrow][lcol + 4] = *(const float4*)(kp + 4);
        *(float4*)&vs[lrow][lcol]     = *(const float4*)vp;
        *(float4*)&vs[lrow][lcol + 4] = *(const float4*)(vp + 4);
        __syncthreads();
        #pragma unroll
        for (int s = 0; s < 32; s++) {
            float4 kj4 = *(const float4*)&ks[s][tj];
            float4 vk4 = *(const float4*)&vs[s][tk];
            float kj[4] = {kj4.x, kj4.y, kj4.z, kj4.w};
            float vk[4] = {vk4.x, vk4.y, vk4.z, vk4.w};
            #pragma unroll
            for (int i = 0; i < 4; i++)
                #pragma unroll
                for (int j = 0; j < 4; j++)
                    acc[i][j] = fmaf(kj[i], vk[j], acc[i][j]);
        }
    }
    float* Mout = g_Mpart[bh * KVP + blockIdx.y];
    #pragma unroll
    for (int i = 0; i < 4; i++)
        #pragma unroll
        for (int j = 0; j < 4; j++)
            Mout[(tj + i) * DKK + tk + j] = acc[i][j];
}

// flat 256-block reduce: one float4 output per thread
__global__ __launch_bounds__(256) void reduce_M() {
    int t = blockIdx.x * 256 + threadIdx.x;      // 0 .. 65535 float4 outputs
    int bh = t >> 10;                            // 1024 float4 per bh
    int e4 = t & 1023;
    float4 s = make_float4(0.f, 0.f, 0.f, 0.f);
    #pragma unroll
    for (int c = 0; c < KVP; c++) {
        float4 p = *(const float4*)&g_Mpart[bh * KVP + c][e4 * 4];
        s.x += p.x; s.y += p.y; s.z += p.z; s.w += p.w;
    }
    *(float4*)&g_M[bh][e4 * 4] = s;
}

// ---------------------------------------------------------------------------
// heads = softmax_k( (Qh @ M) / 8 ), written as swizzled fp16 hi panels only
// (the wo GEMM runs 2-pass and never reads A_lo)
// ---------------------------------------------------------------------------
__global__ __launch_bounds__(256) void qm_softmax() {
    int bh = blockIdx.x;
    int b = bh >> 4, h = bh & 15;

    __shared__ float Ms[DKK * DKK];
    __shared__ float qs[8][DKK];

    int tid = threadIdx.x;
    const float4* Msrc = (const float4*)g_M[bh];
    for (int i = tid; i < (DKK * DKK) / 4; i += 256)
        ((float4*)Ms)[i] = Msrc[i];
    __syncthreads();

    int warp = tid >> 5, lane = tid & 31;
    int sbase = blockIdx.y * 128;

    for (int it = 0; it < 16; it++) {
        int s = sbase + (it << 3) + warp;
        const float* qrow = g_qh + ((size_t)(b * SS + s)) * DD + h * DKK;
        qs[warp][lane]      = qrow[lane];
        qs[warp][lane + 32] = qrow[lane + 32];
        __syncwarp();

        float o0 = 0.0f, o1 = 0.0f;
        #pragma unroll
        for (int j = 0; j < 64; j++) {
            float qv = qs[warp][j];
            o0 = fmaf(qv, Ms[(j << 6) + lane],      o0);
            o1 = fmaf(qv, Ms[(j << 6) + lane + 32], o1);
        }
        o0 *= 0.125f;
        o1 *= 0.125f;

        float mx = fmaxf(o0, o1);
        #pragma unroll
        for (int off = 16; off; off >>= 1)
            mx = fmaxf(mx, __shfl_xor_sync(0xffffffffu, mx, off));
        float e0 = __expf(o0 - mx), e1 = __expf(o1 - mx);
        float sm = e0 + e1;
        #pragma unroll
        for (int off = 16; off; off >>= 1)
            sm += __shfl_xor_sync(0xffffffffu, sm, off);
        float inv = 1.0f / sm;

        // write hi panel only (pre-swizzled)
        int mrow = b * SS + s;
        int mt = mrow >> 7, prow = mrow & 127;
        uint32_t off0 = (uint32_t)prow * 64 + lane * 2;
        uint32_t sw0 = sw64(off0) >> 1;
        size_t d0 = ((size_t)(mt * 32 + h * 2))     * TILEH + sw0;
        size_t d1 = ((size_t)(mt * 32 + h * 2 + 1)) * TILEH + sw0;
        g_pan[3][0][d0] = __float2half_rn(e0 * inv);
        g_pan[3][0][d1] = __float2half_rn(e1 * inv);
        __syncwarp();
    }
}

// ---------------------------------------------------------------------------
extern "C" void kernel_launch(void* const* d_in, const int* in_sizes, int n_in,
                              void* d_out, int out_size) {
    const float* q    = (const float*)d_in[0];
    const float* k    = (const float*)d_in[1];
    const float* v    = (const float*)d_in[2];
    const float* wq_w = (const float*)d_in[3];
    const float* wq_b = (const float*)d_in[4];
    const float* wk_w = (const float*)d_in[5];
    const float* wk_b = (const float*)d_in[6];
    const float* wv_w = (const float*)d_in[7];
    const float* wv_b = (const float*)d_in[8];
    const float* wo_w = (const float*)d_in[9];
    const float* wo_b = (const float*)d_in[10];
    float* out = (float*)d_out;

    const int SMEM_BYTES = NSTG * CHB + 64;   // 98368
    cudaFuncSetAttribute(mma_gemm, cudaFuncAttributeMaxDynamicSharedMemorySize, SMEM_BYTES);

    // fused weight + activation prep (8192 blocks)
    prep_all<<<8192, 256>>>(wq_w, wk_w, wv_w, wo_w, q, k, v);

    // fused QKV projection GEMMs (3-pass split)
    mma_gemm<<<dim3(24, 64), 256, SMEM_BYTES>>>(wq_b, wk_b, wv_b, nullptr, nullptr, 0);

    kv_outer<<<dim3(BB * HH, KVP), 256>>>();
    reduce_M<<<256, 256>>>();
    qm_softmax<<<dim3(BB * HH, SS / 128), 256>>>();   // writes g_pan[3] hi only

    // output projection (2-pass split)
    mma_gemm<<<dim3(8, 64), 256, SMEM_BYTES>>>(nullptr, nullptr, nullptr, wo_b, out, 1);
}

// round 11
// speedup vs baseline: 1.3719x; 1.1765x over previous
#include <cuda_runtime.h>
#include <cuda_fp16.h>
#include <cstdint>

#define BB 4
#define SS 2048
#define DD 1024
#define HH 16
#define DKK 64
#define MR (BB*SS)   // 8192

#define MT 128
#define NT 128
#define NCH 32
#define TILEH 4096           // halves per 128x32 tile
#define TILEB 8192           // bytes per tile
#define CHB (4*TILEB)        // stage: Ahi|Alo|Bhi|Blo = 32KB
#define NSTG 3
#define KVP 16               // kv_outer partials

// ---------------- device scratch ----------------
__device__ __half g_wt[4][2][DD*DD];    // weight panels (x32 scaled, split hi/lo)
__device__ __half g_pan[4][2][MR*DD];   // activation panels: 0=q 1=k 2=v 3=softmax-out
__device__ float g_qh[MR*DD];
__device__ float g_kh[MR*DD];
__device__ float g_vh[MR*DD];
__device__ float g_Mpart[BB*HH*KVP][DKK*DKK];
__device__ float g_M[BB*HH][DKK*DKK];

// ---------------- helpers ----------------
__device__ __forceinline__ uint32_t smem_u32(const void* p) {
    uint32_t a;
    asm("{ .reg .u64 t; cvta.to.shared.u64 t, %1; cvt.u32.u64 %0, t; }" : "=r"(a) : "l"(p));
    return a;
}
#define MBAR_INIT(a, c) asm volatile("mbarrier.init.shared.b64 [%0], %1;" :: "r"(a), "r"(c) : "memory")
#define MBAR_WAIT(a, ph) do { \
    asm volatile("{\n\t.reg .pred P;\n\tWL%=:\n\t" \
        "mbarrier.try_wait.parity.shared.b64 P, [%0], %1;\n\t" \
        "@!P bra WL%=;\n\t}" :: "r"(a), "r"(ph) : "memory"); } while (0)
#define EXPECT_TX(a, n) asm volatile( \
    "mbarrier.arrive.expect_tx.shared.b64 _, [%0], %1;" :: "r"(a), "r"(n) : "memory")
#define BULK(dst, src, n, bar) asm volatile( \
    "cp.async.bulk.shared::cluster.global.mbarrier::complete_tx::bytes [%0], [%1], %2, [%3];" \
    :: "r"(dst), "l"(src), "r"(n), "r"(bar) : "memory")
#define LDSM4(r, a) asm volatile( \
    "ldmatrix.sync.aligned.m8n8.x4.shared.b16 {%0,%1,%2,%3}, [%4];" \
    : "=r"((r)[0]), "=r"((r)[1]), "=r"((r)[2]), "=r"((r)[3]) : "r"(a))
#define LDSM4T(r, a) asm volatile( \
    "ldmatrix.sync.aligned.m8n8.x4.trans.shared.b16 {%0,%1,%2,%3}, [%4];" \
    : "=r"((r)[0]), "=r"((r)[1]), "=r"((r)[2]), "=r"((r)[3]) : "r"(a))
#define MMAF16(d, a, b0, b1) asm volatile( \
    "mma.sync.aligned.m16n8k16.row.col.f32.f16.f16.f32 " \
    "{%0,%1,%2,%3}, {%4,%5,%6,%7}, {%8,%9}, {%0,%1,%2,%3};" \
    : "+f"((d)[0]), "+f"((d)[1]), "+f"((d)[2]), "+f"((d)[3]) \
    : "r"((a)[0]), "r"((a)[1]), "r"((a)[2]), "r"((a)[3]), "r"(b0), "r"(b1))

// swizzle for 64B rows
__device__ __forceinline__ uint32_t sw64(uint32_t off) {
    return off ^ ((off >> 3) & 0x30);
}
// swizzle for 128B rows
__device__ __forceinline__ uint32_t sw128(uint32_t off) {
    return off ^ ((off >> 3) & 0x70);
}
__device__ __forceinline__ uint2 split4(float4 f, uint2& lo_out) {
    __half h0 = __float2half_rn(f.x), h1 = __float2half_rn(f.y);
    __half h2 = __float2half_rn(f.z), h3 = __float2half_rn(f.w);
    __half l0 = __float2half_rn(f.x - __half2float(h0));
    __half l1 = __float2half_rn(f.y - __half2float(h1));
    __half l2 = __float2half_rn(f.z - __half2float(h2));
    __half l3 = __float2half_rn(f.w - __half2float(h3));
    __half2 p0 = __halves2half2(h0, h1), p1 = __halves2half2(h2, h3);
    __half2 q0 = __halves2half2(l0, l1), q1 = __halves2half2(l2, l3);
    uint2 hi; hi.x = *(uint32_t*)&p0; hi.y = *(uint32_t*)&p1;
    lo_out.x = *(uint32_t*)&q0; lo_out.y = *(uint32_t*)&q1;
    return hi;
}

// ---------------------------------------------------------------------------
// fused prep: blocks [0, 4096) do weights; blocks [4096, 8192) do q/k/v split
// ---------------------------------------------------------------------------
__global__ void prep_all(const float* __restrict__ wq, const float* __restrict__ wk,
                         const float* __restrict__ wv, const float* __restrict__ wo,
                         const float* __restrict__ q, const float* __restrict__ k,
                         const float* __restrict__ v) {
    if (blockIdx.x < 4096) {
        int idx = blockIdx.x * 256 + threadIdx.x;      // n*1024 + kq
        int n = idx >> 10, kq = idx & 1023;
        int h = n >> 6, dk = n & 63;
        int src = h * (DD * DKK) + kq * DKK + dk;      // w[h][kq][dk]
        uint32_t off = (n & 127) * 64 + (kq & 31) * 2;
        size_t d = ((size_t)((n >> 7) * 32 + (kq >> 5))) * TILEH + (sw64(off) >> 1);
        float vals[4] = { wq[src] * 32.0f, wk[src] * 32.0f, wv[src] * 32.0f,
                          wo[n * DD + kq] * 32.0f };
        #pragma unroll
        for (int w = 0; w < 4; w++) {
            __half hi = __float2half_rn(vals[w]);
            __half lo = __float2half_rn(vals[w] - __half2float(hi));
            g_wt[w][0][d] = hi;
            g_wt[w][1][d] = lo;
        }
    } else {
        int idx = (blockIdx.x - 4096) * 256 + threadIdx.x;
        int m = idx >> 7;
        int k0 = (idx & 127) << 3;
        uint32_t off = (m & 127) * 64 + (k0 & 31) * 2;
        size_t d = ((size_t)((m >> 7) * 32 + (k0 >> 5))) * TILEH + (sw64(off) >> 1);
        size_t s = (size_t)m * DD + k0;
        const float* srcs[3] = { q + s, k + s, v + s };
        #pragma unroll
        for (int w = 0; w < 3; w++) {
            float f[8];
            *(float4*)&f[0] = *(const float4*)(srcs[w]);
            *(float4*)&f[4] = *(const float4*)(srcs[w] + 4);
            __half hi[8], lo[8];
            #pragma unroll
            for (int i = 0; i < 8; i++) {
                hi[i] = __float2half_rn(f[i]);
                lo[i] = __float2half_rn(f[i] - __half2float(hi[i]));
            }
            *(uint4*)&g_pan[w][0][d] = *(uint4*)hi;
            *(uint4*)&g_pan[w][1][d] = *(uint4*)lo;
        }
    }
}

// ---------------------------------------------------------------------------
// split fp16 mma.sync GEMM (unchanged from R10)
// ---------------------------------------------------------------------------
__global__ __launch_bounds__(256, 2) void mma_gemm(
        const float* __restrict__ b0p, const float* __restrict__ b1p,
        const float* __restrict__ b2p, const float* __restrict__ bwp,
        float* __restrict__ Oout, int mode) {
    extern __shared__ char smem[];
    int widx, nIdx;
    const float* bias;
    float* C;
    if (mode == 0) {
        widx = blockIdx.x >> 3;
        nIdx = blockIdx.x & 7;
        bias = (widx == 0) ? b0p : (widx == 1) ? b1p : b2p;
        C = (widx == 0) ? g_qh : (widx == 1) ? g_kh : g_vh;
    } else {
        widx = 3;
        nIdx = blockIdx.x;
        bias = bwp;
        C = Oout;
    }
    const __half* Ahi = g_pan[widx][0];
    const __half* Alo = g_pan[widx][1];
    const __half* Bhi = g_wt[widx][0];
    const __half* Blo = g_wt[widx][1];

    const uint32_t s0 = smem_u32(smem);
    const uint32_t mb = s0 + NSTG * CHB;

    const int tid = threadIdx.x;
    const int wid = tid >> 5, lane = tid & 31;
    const int bm = blockIdx.y * MT, bn = nIdx * NT;
    const int m0 = (wid >> 2) * 64;
    const int n0 = (wid & 3) * 32;

    if (tid == 0) { MBAR_INIT(mb, 1); MBAR_INIT(mb + 8, 1); MBAR_INIT(mb + 16, 1); }
    __syncthreads();

    const uint32_t stage_bytes = (mode == 0) ? 4u * TILEB : 3u * TILEB;
    auto issue = [&](int ch, int stg) {
        uint32_t sb = s0 + stg * CHB;
        uint32_t bar = mb + stg * 8;
        EXPECT_TX(bar, stage_bytes);
        const __half* a0 = Ahi + ((size_t)(blockIdx.y * 32 + ch)) * TILEH;
        const __half* w0 = Bhi + ((size_t)(nIdx * 32 + ch)) * TILEH;
        const __half* w1 = Blo + ((size_t)(nIdx * 32 + ch)) * TILEH;
        BULK(sb,             a0, TILEB, bar);
        if (mode == 0) {
            const __half* a1 = Alo + ((size_t)(blockIdx.y * 32 + ch)) * TILEH;
            BULK(sb + TILEB, a1, TILEB, bar);
        }
        BULK(sb + 2 * TILEB, w0, TILEB, bar);
        BULK(sb + 3 * TILEB, w1, TILEB, bar);
    };
    if (tid == 0) { issue(0, 0); issue(1, 1); }

    const int rowA = m0 + (lane & 7) + ((lane >> 3) & 1) * 8;
    const uint32_t cA = ((lane >> 4) & 1) * 16;
    const uint32_t xswA = (uint32_t)(rowA & 6) << 3;
    const uint32_t aRow = (uint32_t)rowA * 64;
    const int rowB = n0 + ((lane >> 4) << 3) + (lane & 7);
    const uint32_t cB = ((lane >> 3) & 1) * 16;
    const uint32_t xswB = (uint32_t)(rowB & 6) << 3;
    const uint32_t bRow = (uint32_t)rowB * 64;

    float acc[4][4][4];
    #pragma unroll
    for (int i = 0; i < 4; i++)
        #pragma unroll
        for (int j = 0; j < 4; j++)
            #pragma unroll
            for (int r = 0; r < 4; r++) acc[i][j][r] = 0.0f;

    for (int c = 0; c < NCH; ++c) {
        int stg = c % 3;
        uint32_t sb = s0 + stg * CHB;
        MBAR_WAIT(mb + stg * 8, (c / 3) & 1);
        if (tid == 0 && c + 2 < NCH) issue(c + 2, (c + 2) % 3);

        #pragma unroll
        for (int ks = 0; ks < 2; ks++) {
            const uint32_t aoff = aRow + (((uint32_t)(ks * 32) + cA) ^ xswA);
            const uint32_t boff = bRow + (((uint32_t)(ks * 32) + cB) ^ xswB);
            uint32_t ah[4][4], al[4][4], bh[2][4], bl[2][4];
            #pragma unroll
            for (int i = 0; i < 4; i++) LDSM4(ah[i], sb + aoff + i * 1024);
            #pragma unroll
            for (int g = 0; g < 2; g++) LDSM4(bh[g], sb + 2 * TILEB + boff + g * 1024);
            #pragma unroll
            for (int i = 0; i < 4; i++) {
                MMAF16(acc[i][0], ah[i], bh[0][0], bh[0][1]);
                MMAF16(acc[i][1], ah[i], bh[0][2], bh[0][3]);
                MMAF16(acc[i][2], ah[i], bh[1][0], bh[1][1]);
                MMAF16(acc[i][3], ah[i], bh[1][2], bh[1][3]);
            }
            #pragma unroll
            for (int g = 0; g < 2; g++) LDSM4(bl[g], sb + 3 * TILEB + boff + g * 1024);
            #pragma unroll
            for (int i = 0; i < 4; i++) {
                MMAF16(acc[i][0], ah[i], bl[0][0], bl[0][1]);
                MMAF16(acc[i][1], ah[i], bl[0][2], bl[0][3]);
                MMAF16(acc[i][2], ah[i], bl[1][0], bl[1][1]);
                MMAF16(acc[i][3], ah[i], bl[1][2], bl[1][3]);
            }
            if (mode == 0) {
                #pragma unroll
                for (int i = 0; i < 4; i++) LDSM4(al[i], sb + TILEB + aoff + i * 1024);
                #pragma unroll
                for (int i = 0; i < 4; i++) {
                    MMAF16(acc[i][0], al[i], bh[0][0], bh[0][1]);
                    MMAF16(acc[i][1], al[i], bh[0][2], bh[0][3]);
                    MMAF16(acc[i][2], al[i], bh[1][0], bh[1][1]);
                    MMAF16(acc[i][3], al[i], bh[1][2], bh[1][3]);
                }
            }
        }
        __syncthreads();
    }

    #pragma unroll
    for (int i = 0; i < 4; i++) {
        int row0 = bm + m0 + i * 16 + (lane >> 2);
        #pragma unroll
        for (int jj = 0; jj < 4; jj++) {
            int col = bn + n0 + jj * 8 + (lane & 3) * 2;
            float2 bv = *(const float2*)(bias + col);
            float2 r0, r1;
            r0.x = acc[i][jj][0] * 0.03125f + bv.x;  r0.y = acc[i][jj][1] * 0.03125f + bv.y;
            r1.x = acc[i][jj][2] * 0.03125f + bv.x;  r1.y = acc[i][jj][3] * 0.03125f + bv.y;
            *(float2*)(C + (size_t)row0 * DD + col) = r0;
            *(float2*)(C + (size_t)(row0 + 8) * DD + col) = r1;
        }
    }
}

// ---------------------------------------------------------------------------
// kv_outer via tensor cores: M_part[bh][sy] = K_tile^T @ V_tile (3-pass fp16)
// tiles [128 s][64 dk] fp16 hi/lo in smem (128B rows, SW128), ldmatrix.trans.
// grid (64, 16), 128 threads (4 warps, 2x2).
// ---------------------------------------------------------------------------
__global__ __launch_bounds__(128) void kv_outer_mma() {
    extern __shared__ char smem[];
    const uint32_t sK0 = smem_u32(smem);            // K hi
    const uint32_t sK1 = sK0 + 16384;               // K lo
    const uint32_t sV0 = sK0 + 32768;               // V hi
    const uint32_t sV1 = sK0 + 49152;               // V lo

    int bh = blockIdx.x;
    int b = bh >> 4, h = bh & 15;
    int sy = blockIdx.y;
    int tid = threadIdx.x;
    int wid = tid >> 5, lane = tid & 31;
    int wm = wid >> 1, wn = wid & 1;

    const float* Kg = g_kh + ((size_t)b * SS + sy * 128) * DD + h * DKK;
    const float* Vg = g_vh + ((size_t)b * SS + sy * 128) * DD + h * DKK;

    // convert: 128 rows x 64 cols, 4 floats per thread-iter
    #pragma unroll
    for (int i = 0; i < 16; i++) {
        int idx = tid + i * 128;
        int s = idx >> 4, c4 = (idx & 15) << 2;
        uint32_t sw = sw128((uint32_t)s * 128 + c4 * 2);
        uint2 lo;
        uint2 hi = split4(*(const float4*)(Kg + (size_t)s * DD + c4), lo);
        *(uint2*)(smem + sw) = hi;
        *(uint2*)(smem + 16384 + sw) = lo;
        hi = split4(*(const float4*)(Vg + (size_t)s * DD + c4), lo);
        *(uint2*)(smem + 32768 + sw) = hi;
        *(uint2*)(smem + 49152 + sw) = lo;
    }
    __syncthreads();

    // A (K^T, m=dk of K): trans-load lane mapping
    //   srow = K0 + (lane&7) + ((lane>>4)<<3) ; col = M0 + ((lane>>3)&1)*8
    const uint32_t a_srow = (uint32_t)((lane & 7) + ((lane >> 4) << 3));
    const uint32_t a_xsw = (a_srow & 7) << 4;
    uint32_t aOff[2];
    #pragma unroll
    for (int mi = 0; mi < 2; mi++) {
        uint32_t col = (uint32_t)(wm * 32 + mi * 16 + ((lane >> 3) & 1) * 8);
        aOff[mi] = a_srow * 128 + ((col * 2) ^ a_xsw);
    }
    // B (V, n=dk of V): srow = K0 + (lane&7) + ((lane>>3)&1)*8 ; col = N0 + ((lane>>4)&1)*8
    const uint32_t b_srow = (uint32_t)((lane & 7) + (((lane >> 3) & 1) << 3));
    const uint32_t b_xsw = (b_srow & 7) << 4;
    uint32_t bOff[2];
    #pragma unroll
    for (int g = 0; g < 2; g++) {
        uint32_t col = (uint32_t)(wn * 32 + g * 16 + ((lane >> 4) & 1) * 8);
        bOff[g] = b_srow * 128 + ((col * 2) ^ b_xsw);
    }

    float acc[2][4][4];
    #pragma unroll
    for (int i = 0; i < 2; i++)
        #pragma unroll
        for (int j = 0; j < 4; j++)
            #pragma unroll
            for (int r = 0; r < 4; r++) acc[i][j][r] = 0.0f;

    #pragma unroll
    for (int st = 0; st < 8; st++) {
        uint32_t base = (uint32_t)st * 2048;   // 16 s-rows * 128B
        uint32_t kh[2][4], kl[2][4], vh[2][4], vl[2][4];
        #pragma unroll
        for (int mi = 0; mi < 2; mi++) LDSM4T(kh[mi], sK0 + base + aOff[mi]);
        #pragma unroll
        for (int g = 0; g < 2; g++)  LDSM4T(vh[g], sV0 + base + bOff[g]);
        #pragma unroll
        for (int mi = 0; mi < 2; mi++) {
            MMAF16(acc[mi][0], kh[mi], vh[0][0], vh[0][1]);
            MMAF16(acc[mi][1], kh[mi], vh[0][2], vh[0][3]);
            MMAF16(acc[mi][2], kh[mi], vh[1][0], vh[1][1]);
            MMAF16(acc[mi][3], kh[mi], vh[1][2], vh[1][3]);
        }
        #pragma unroll
        for (int g = 0; g < 2; g++)  LDSM4T(vl[g], sV1 + base + bOff[g]);
        #pragma unroll
        for (int mi = 0; mi < 2; mi++) {
            MMAF16(acc[mi][0], kh[mi], vl[0][0], vl[0][1]);
            MMAF16(acc[mi][1], kh[mi], vl[0][2], vl[0][3]);
            MMAF16(acc[mi][2], kh[mi], vl[1][0], vl[1][1]);
            MMAF16(acc[mi][3], kh[mi], vl[1][2], vl[1][3]);
        }
        #pragma unroll
        for (int mi = 0; mi < 2; mi++) LDSM4T(kl[mi], sK1 + base + aOff[mi]);
        #pragma unroll
        for (int mi = 0; mi < 2; mi++) {
            MMAF16(acc[mi][0], kl[mi], vh[0][0], vh[0][1]);
            MMAF16(acc[mi][1], kl[mi], vh[0][2], vh[0][3]);
            MMAF16(acc[mi][2], kl[mi], vh[1][0], vh[1][1]);
            MMAF16(acc[mi][3], kl[mi], vh[1][2], vh[1][3]);
        }
    }

    float* Mout = g_Mpart[bh * KVP + sy];
    #pragma unroll
    for (int mi = 0; mi < 2; mi++) {
        int row = wm * 32 + mi * 16 + (lane >> 2);
        #pragma unroll
        for (int ng = 0; ng < 4; ng++) {
            int col = wn * 32 + ng * 8 + (lane & 3) * 2;
            Mout[row * DKK + col]           = acc[mi][ng][0];
            Mout[row * DKK + col + 1]       = acc[mi][ng][1];
            Mout[(row + 8) * DKK + col]     = acc[mi][ng][2];
            Mout[(row + 8) * DKK + col + 1] = acc[mi][ng][3];
        }
    }
}

// flat 256-block reduce
__global__ __launch_bounds__(256) void reduce_M() {
    int t = blockIdx.x * 256 + threadIdx.x;
    int bh = t >> 10;
    int e4 = t & 1023;
    float4 s = make_float4(0.f, 0.f, 0.f, 0.f);
    #pragma unroll
    for (int c = 0; c < KVP; c++) {
        float4 p = *(const float4*)&g_Mpart[bh * KVP + c][e4 * 4];
        s.x += p.x; s.y += p.y; s.z += p.z; s.w += p.w;
    }
    *(float4*)&g_M[bh][e4 * 4] = s;
}

// ---------------------------------------------------------------------------
// qm_softmax via tensor cores: out = softmax((Qrows @ M)/8), fp16 3-pass.
// Q tile [128 s][64 dk] (A, non-trans), M tile [64 j][64 n] (B, trans).
// grid (64, 16), 256 threads (8 warps x 16 rows).
// ---------------------------------------------------------------------------
__global__ __launch_bounds__(256) void qm_softmax_mma() {
    extern __shared__ char smem[];
    const uint32_t sQ0 = smem_u32(smem);        // Q hi 16KB
    const uint32_t sQ1 = sQ0 + 16384;           // Q lo 16KB
    const uint32_t sM0 = sQ0 + 32768;           // M hi 8KB
    const uint32_t sM1 = sQ0 + 40960;           // M lo 8KB

    int bh = blockIdx.x;
    int b = bh >> 4, h = bh & 15;
    int sy = blockIdx.y;
    int tid = threadIdx.x;
    int wid = tid >> 5, lane = tid & 31;

    // convert M (64x64)
    #pragma unroll
    for (int i = 0; i < 4; i++) {
        int idx = tid + i * 256;
        int j = idx >> 4, c4 = (idx & 15) << 2;
        uint32_t sw = sw128((uint32_t)j * 128 + c4 * 2);
        uint2 lo;
        uint2 hi = split4(*(const float4*)&g_M[bh][j * DKK + c4], lo);
        *(uint2*)(smem + 32768 + sw) = hi;
        *(uint2*)(smem + 40960 + sw) = lo;
    }
    // convert Q rows (128x64)
    const float* Qg = g_qh + ((size_t)b * SS + sy * 128) * DD + h * DKK;
    #pragma unroll
    for (int i = 0; i < 8; i++) {
        int idx = tid + i * 256;
        int s = idx >> 4, c4 = (idx & 15) << 2;
        uint32_t sw = sw128((uint32_t)s * 128 + c4 * 2);
        uint2 lo;
        uint2 hi = split4(*(const float4*)(Qg + (size_t)s * DD + c4), lo);
        *(uint2*)(smem + sw) = hi;
        *(uint2*)(smem + 16384 + sw) = lo;
    }
    __syncthreads();

    // A: non-trans, rows = warp's 16 q-rows
    const int a_row = wid * 16 + (lane & 7) + ((lane >> 3) & 1) * 8;
    const uint32_t a_base = (uint32_t)a_row * 128;
    const uint32_t a_xsw = ((uint32_t)a_row & 7) << 4;
    const uint32_t a_c = ((lane >> 4) & 1) * 16;
    // B: trans from [j][n]
    const uint32_t b_srow = (uint32_t)((lane & 7) + (((lane >> 3) & 1) << 3));
    const uint32_t b_xsw = (b_srow & 7) << 4;
    uint32_t bOff[4];
    #pragma unroll
    for (int g = 0; g < 4; g++) {
        uint32_t col = (uint32_t)(g * 16 + ((lane >> 4) & 1) * 8);
        bOff[g] = b_srow * 128 + ((col * 2) ^ b_xsw);
    }

    float acc[8][4];
    #pragma unroll
    for (int j = 0; j < 8; j++)
        #pragma unroll
        for (int r = 0; r < 4; r++) acc[j][r] = 0.0f;

    #pragma unroll
    for (int st = 0; st < 4; st++) {
        uint32_t aoff = a_base + (((uint32_t)st * 32 + a_c) ^ a_xsw);
        uint32_t bbase = (uint32_t)st * 2048;
        uint32_t qh4[4], ql4[4], mh[4][4], ml[4][4];
        LDSM4(qh4, sQ0 + aoff);
        #pragma unroll
        for (int g = 0; g < 4; g++) LDSM4T(mh[g], sM0 + bbase + bOff[g]);
        #pragma unroll
        for (int g = 0; g < 4; g++) {
            MMAF16(acc[g * 2 + 0], qh4, mh[g][0], mh[g][1]);
            MMAF16(acc[g * 2 + 1], qh4, mh[g][2], mh[g][3]);
        }
        #pragma unroll
        for (int g = 0; g < 4; g++) LDSM4T(ml[g], sM1 + bbase + bOff[g]);
        #pragma unroll
        for (int g = 0; g < 4; g++) {
            MMAF16(acc[g * 2 + 0], qh4, ml[g][0], ml[g][1]);
            MMAF16(acc[g * 2 + 1], qh4, ml[g][2], ml[g][3]);
        }
        LDSM4(ql4, sQ1 + aoff);
        #pragma unroll
        for (int g = 0; g < 4; g++) {
            MMAF16(acc[g * 2 + 0], ql4, mh[g][0], mh[g][1]);
            MMAF16(acc[g * 2 + 1], ql4, mh[g][2], mh[g][3]);
        }
    }

    // softmax over the 64 cols of each row; thread holds 2 rows x 16 cols
    float mx0 = -1e30f, mx1 = -1e30f;
    #pragma unroll
    for (int f = 0; f < 8; f++) {
        acc[f][0] *= 0.125f; acc[f][1] *= 0.125f;
        acc[f][2] *= 0.125f; acc[f][3] *= 0.125f;
        mx0 = fmaxf(mx0, fmaxf(acc[f][0], acc[f][1]));
        mx1 = fmaxf(mx1, fmaxf(acc[f][2], acc[f][3]));
    }
    #pragma unroll
    for (int o = 1; o <= 2; o <<= 1) {
        mx0 = fmaxf(mx0, __shfl_xor_sync(0xffffffffu, mx0, o));
        mx1 = fmaxf(mx1, __shfl_xor_sync(0xffffffffu, mx1, o));
    }
    float sm0 = 0.0f, sm1 = 0.0f;
    #pragma unroll
    for (int f = 0; f < 8; f++) {
        acc[f][0] = __expf(acc[f][0] - mx0); acc[f][1] = __expf(acc[f][1] - mx0);
        acc[f][2] = __expf(acc[f][2] - mx1); acc[f][3] = __expf(acc[f][3] - mx1);
        sm0 += acc[f][0] + acc[f][1];
        sm1 += acc[f][2] + acc[f][3];
    }
    #pragma unroll
    for (int o = 1; o <= 2; o <<= 1) {
        sm0 += __shfl_xor_sync(0xffffffffu, sm0, o);
        sm1 += __shfl_xor_sync(0xffffffffu, sm1, o);
    }
    float inv0 = 1.0f / sm0, inv1 = 1.0f / sm1;

    // write fp16-hi panel (wo GEMM is 2-pass, lo unused)
    int mt = b * 16 + sy;
    int prow0 = wid * 16 + (lane >> 2);
    #pragma unroll
    for (int f = 0; f < 8; f++) {
        int cc = f * 8 + (lane & 3) * 2;
        int chunk = 2 * h + (cc >> 5);
        uint32_t cwi = (uint32_t)(cc & 31);
        size_t tbase = ((size_t)(mt * 32 + chunk)) * TILEH;
        uint32_t off0 = sw64((uint32_t)prow0 * 64 + cwi * 2) >> 1;
        uint32_t off1 = sw64((uint32_t)(prow0 + 8) * 64 + cwi * 2) >> 1;
        __half2 v0 = __halves2half2(__float2half_rn(acc[f][0] * inv0),
                                    __float2half_rn(acc[f][1] * inv0));
        __half2 v1 = __halves2half2(__float2half_rn(acc[f][2] * inv1),
                                    __float2half_rn(acc[f][3] * inv1));
        *(__half2*)&g_pan[3][0][tbase + off0] = v0;
        *(__half2*)&g_pan[3][0][tbase + off1] = v1;
    }
}

// ---------------------------------------------------------------------------
extern "C" void kernel_launch(void* const* d_in, const int* in_sizes, int n_in,
                              void* d_out, int out_size) {
    const float* q    = (const float*)d_in[0];
    const float* k    = (const float*)d_in[1];
    const float* v    = (const float*)d_in[2];
    const float* wq_w = (const float*)d_in[3];
    const float* wq_b = (const float*)d_in[4];
    const float* wk_w = (const float*)d_in[5];
    const float* wk_b = (const float*)d_in[6];
    const float* wv_w = (const float*)d_in[7];
    const float* wv_b = (const float*)d_in[8];
    const float* wo_w = (const float*)d_in[9];
    const float* wo_b = (const float*)d_in[10];
    float* out = (float*)d_out;

    const int SMEM_BYTES = NSTG * CHB + 64;   // 98368
    cudaFuncSetAttribute(mma_gemm, cudaFuncAttributeMaxDynamicSharedMemorySize, SMEM_BYTES);
    cudaFuncSetAttribute(kv_outer_mma, cudaFuncAttributeMaxDynamicSharedMemorySize, 65536);
    cudaFuncSetAttribute(qm_softmax_mma, cudaFuncAttributeMaxDynamicSharedMemorySize, 49152);

    prep_all<<<8192, 256>>>(wq_w, wk_w, wv_w, wo_w, q, k, v);

    mma_gemm<<<dim3(24, 64), 256, SMEM_BYTES>>>(wq_b, wk_b, wv_b, nullptr, nullptr, 0);

    kv_outer_mma<<<dim3(BB * HH, KVP), 128, 65536>>>();
    reduce_M<<<256, 256>>>();
    qm_softmax_mma<<<dim3(BB * HH, 16), 256, 49152>>>();

    mma_gemm<<<dim3(8, 64), 256, SMEM_BYTES>>>(nullptr, nullptr, nullptr, wo_b, out, 1);
}